// round 1
// baseline (speedup 1.0000x reference)
#include <cuda_runtime.h>

// Problem constants
#define Nn 2
#define Ll 2048
#define Ee 1024
#define Hh 16
#define Dd 64

// Attention tiling
#define BM 64     // query rows per CTA
#define BKT 64    // key rows per tile
#define SP 65     // smem row stride (pad to dodge bank conflicts)

// Intermediate attention output [N, L, E] (pre-projection). Static device
// scratch: allocation-free per harness rules.
__device__ float g_attn_out[(size_t)Nn * Ll * Ee];

// ---------------------------------------------------------------------------
// Fused flash-attention kernel (fp32, online softmax).
// Grid: (L/BM, N*H). Block: 256 threads as 16x16; each thread owns a 4x4
// micro-tile of S/P and of the O accumulator.
// Smem layouts put the warp-uniform loop index on the ROW so inner-loop LDS
// patterns are broadcast/2-way at worst:
//   Qt[d][m], Kt[d][c]   (transposed on load)
//   Vs[kk][dcol]         (natural)
//   Pt[kk][m]            (P written transposed)
// ---------------------------------------------------------------------------
__global__ __launch_bounds__(256) void attn_kernel(
    const float* __restrict__ Q, const float* __restrict__ K,
    const float* __restrict__ V, const int* __restrict__ M)
{
    extern __shared__ float sm[];
    float* Qt = sm;               // [Dd][SP]
    float* Kt = Qt + Dd * SP;     // [Dd][SP]
    float* Vs = Kt + Dd * SP;     // [BKT][SP]
    float* Pt = Vs + BKT * SP;    // [BKT][SP]

    const int tid = threadIdx.x;
    const int tx = tid & 15;
    const int ty = tid >> 4;
    const int n  = blockIdx.y >> 4;   // Hh == 16
    const int h  = blockIdx.y & 15;
    const int q0 = blockIdx.x * BM;

    // ---- load Q tile transposed: Qt[d][m] ----
    const float* qb = Q + ((size_t)(n * Ll + q0)) * Ee + h * Dd;
    for (int idx = tid; idx < BM * (Dd / 4); idx += 256) {
        int r  = idx >> 4;    // query row within tile
        int d4 = idx & 15;    // float4 index along d
        float4 val = *reinterpret_cast<const float4*>(qb + (size_t)r * Ee + d4 * 4);
        Qt[(d4 * 4 + 0) * SP + r] = val.x;
        Qt[(d4 * 4 + 1) * SP + r] = val.y;
        Qt[(d4 * 4 + 2) * SP + r] = val.z;
        Qt[(d4 * 4 + 3) * SP + r] = val.w;
    }

    float acc[4][4];
    #pragma unroll
    for (int i = 0; i < 4; i++)
        #pragma unroll
        for (int j = 0; j < 4; j++) acc[i][j] = 0.0f;

    float mrow[4], lrow[4];
    #pragma unroll
    for (int i = 0; i < 4; i++) { mrow[i] = -1e30f; lrow[i] = 0.0f; }

    const float scale = 0.03125f;  // 1/sqrt(E) = 1/32

    for (int kt = 0; kt < Ll / BKT; kt++) {
        __syncthreads();  // all reads of Kt/Vs/Pt from previous iter done

        // ---- load K tile transposed + V tile natural ----
        const float* kb = K + ((size_t)(n * Ll + kt * BKT)) * Ee + h * Dd;
        const float* vb = V + ((size_t)(n * Ll + kt * BKT)) * Ee + h * Dd;
        for (int idx = tid; idx < BKT * (Dd / 4); idx += 256) {
            int r  = idx >> 4;
            int d4 = idx & 15;
            float4 kv = *reinterpret_cast<const float4*>(kb + (size_t)r * Ee + d4 * 4);
            Kt[(d4 * 4 + 0) * SP + r] = kv.x;
            Kt[(d4 * 4 + 1) * SP + r] = kv.y;
            Kt[(d4 * 4 + 2) * SP + r] = kv.z;
            Kt[(d4 * 4 + 3) * SP + r] = kv.w;
            float4 vv = *reinterpret_cast<const float4*>(vb + (size_t)r * Ee + d4 * 4);
            Vs[r * SP + d4 * 4 + 0] = vv.x;
            Vs[r * SP + d4 * 4 + 1] = vv.y;
            Vs[r * SP + d4 * 4 + 2] = vv.z;
            Vs[r * SP + d4 * 4 + 3] = vv.w;
        }
        __syncthreads();

        // ---- S = Q K^T  (4x4 micro-tile per thread) ----
        float s[4][4];
        #pragma unroll
        for (int i = 0; i < 4; i++)
            #pragma unroll
            for (int j = 0; j < 4; j++) s[i][j] = 0.0f;

        #pragma unroll 8
        for (int d = 0; d < Dd; d++) {
            float qa[4], ka[4];
            #pragma unroll
            for (int i = 0; i < 4; i++) qa[i] = Qt[d * SP + ty * 4 + i];
            #pragma unroll
            for (int j = 0; j < 4; j++) ka[j] = Kt[d * SP + tx * 4 + j];
            #pragma unroll
            for (int i = 0; i < 4; i++)
                #pragma unroll
                for (int j = 0; j < 4; j++) s[i][j] += qa[i] * ka[j];
        }

        // ---- mask + scale ----
        const int* mb = M + (size_t)n * Ll * Ll + (size_t)q0 * Ll + kt * BKT;
        #pragma unroll
        for (int i = 0; i < 4; i++) {
            #pragma unroll
            for (int j = 0; j < 4; j++) {
                int mv = mb[(size_t)(ty * 4 + i) * Ll + tx * 4 + j];
                s[i][j] = (mv != 0) ? s[i][j] * scale : -1e20f;
            }
        }

        // ---- online softmax: row stats via 16-lane butterfly shuffles ----
        #pragma unroll
        for (int i = 0; i < 4; i++) {
            float tm = fmaxf(fmaxf(s[i][0], s[i][1]), fmaxf(s[i][2], s[i][3]));
            #pragma unroll
            for (int off = 8; off >= 1; off >>= 1)
                tm = fmaxf(tm, __shfl_xor_sync(0xffffffffu, tm, off));
            float mnew  = fmaxf(mrow[i], tm);
            float alpha = __expf(mrow[i] - mnew);
            float ts = 0.0f;
            #pragma unroll
            for (int j = 0; j < 4; j++) {
                float p = __expf(s[i][j] - mnew);
                s[i][j] = p;
                ts += p;
            }
            #pragma unroll
            for (int off = 8; off >= 1; off >>= 1)
                ts += __shfl_xor_sync(0xffffffffu, ts, off);
            lrow[i] = lrow[i] * alpha + ts;
            mrow[i] = mnew;
            #pragma unroll
            for (int j = 0; j < 4; j++) acc[i][j] *= alpha;
        }

        // ---- write P transposed: Pt[kk][m] ----
        #pragma unroll
        for (int i = 0; i < 4; i++)
            #pragma unroll
            for (int j = 0; j < 4; j++)
                Pt[(tx * 4 + j) * SP + (ty * 4 + i)] = s[i][j];
        __syncthreads();

        // ---- O += P V ----
        #pragma unroll 8
        for (int kk = 0; kk < BKT; kk++) {
            float pa[4], va[4];
            #pragma unroll
            for (int i = 0; i < 4; i++) pa[i] = Pt[kk * SP + ty * 4 + i];
            #pragma unroll
            for (int j = 0; j < 4; j++) va[j] = Vs[kk * SP + tx * 4 + j];
            #pragma unroll
            for (int i = 0; i < 4; i++)
                #pragma unroll
                for (int j = 0; j < 4; j++) acc[i][j] += pa[i] * va[j];
        }
    }

    // ---- normalize and write [n, q, h*D + d] ----
    float* ob = g_attn_out + ((size_t)(n * Ll + q0)) * Ee + h * Dd;
    #pragma unroll
    for (int i = 0; i < 4; i++) {
        float inv = 1.0f / lrow[i];
        float4 o;
        o.x = acc[i][0] * inv;
        o.y = acc[i][1] * inv;
        o.z = acc[i][2] * inv;
        o.w = acc[i][3] * inv;
        *reinterpret_cast<float4*>(ob + (size_t)(ty * 4 + i) * Ee + tx * 4) = o;
    }
}

// ---------------------------------------------------------------------------
// Output projection: out[m][n] = sum_k X[m][k] * W[n][k] + b[n]
// M=N*L=4096, N=E=1024, K=E=1024. 64x64 tiles, BK=16, 4x4 micro-tiles.
// ---------------------------------------------------------------------------
__global__ __launch_bounds__(256) void proj_kernel(
    const float* __restrict__ W, const float* __restrict__ b,
    float* __restrict__ out)
{
    __shared__ float As[16][SP];  // As[kk][m]
    __shared__ float Bs[16][SP];  // Bs[kk][nn]

    const int tid = threadIdx.x;
    const int tx = tid & 15;
    const int ty = tid >> 4;
    const int n0 = blockIdx.x * 64;
    const int m0 = blockIdx.y * 64;

    const int r  = tid >> 2;  // 0..63 (row within tile for loads)
    const int kq = tid & 3;   // 0..3  (float4 slot along k)

    const float* Ab = g_attn_out + (size_t)(m0 + r) * Ee + kq * 4;
    const float* Bb = W + (size_t)(n0 + r) * Ee + kq * 4;

    float acc[4][4];
    #pragma unroll
    for (int i = 0; i < 4; i++)
        #pragma unroll
        for (int j = 0; j < 4; j++) acc[i][j] = 0.0f;

    for (int k0 = 0; k0 < Ee; k0 += 16) {
        __syncthreads();
        float4 a4 = *reinterpret_cast<const float4*>(Ab + k0);
        As[kq * 4 + 0][r] = a4.x;
        As[kq * 4 + 1][r] = a4.y;
        As[kq * 4 + 2][r] = a4.z;
        As[kq * 4 + 3][r] = a4.w;
        float4 b4 = *reinterpret_cast<const float4*>(Bb + k0);
        Bs[kq * 4 + 0][r] = b4.x;
        Bs[kq * 4 + 1][r] = b4.y;
        Bs[kq * 4 + 2][r] = b4.z;
        Bs[kq * 4 + 3][r] = b4.w;
        __syncthreads();

        #pragma unroll
        for (int kk = 0; kk < 16; kk++) {
            float a[4], bb[4];
            #pragma unroll
            for (int i = 0; i < 4; i++) a[i] = As[kk][ty * 4 + i];
            #pragma unroll
            for (int j = 0; j < 4; j++) bb[j] = Bs[kk][tx * 4 + j];
            #pragma unroll
            for (int i = 0; i < 4; i++)
                #pragma unroll
                for (int j = 0; j < 4; j++) acc[i][j] += a[i] * bb[j];
        }
    }

    float4 bv = *reinterpret_cast<const float4*>(b + n0 + tx * 4);
    #pragma unroll
    for (int i = 0; i < 4; i++) {
        float4 o;
        o.x = acc[i][0] + bv.x;
        o.y = acc[i][1] + bv.y;
        o.z = acc[i][2] + bv.z;
        o.w = acc[i][3] + bv.w;
        *reinterpret_cast<float4*>(out + (size_t)(m0 + ty * 4 + i) * Ee + n0 + tx * 4) = o;
    }
}

extern "C" void kernel_launch(void* const* d_in, const int* in_sizes, int n_in,
                              void* d_out, int out_size)
{
    const float* Q = (const float*)d_in[0];
    const float* K = (const float*)d_in[1];
    const float* V = (const float*)d_in[2];
    const int*   M = (const int*)d_in[3];
    const float* W = (const float*)d_in[4];
    const float* b = (const float*)d_in[5];
    float* out = (float*)d_out;

    const int attn_smem = 4 * BKT * SP * (int)sizeof(float);  // 66560 B
    cudaFuncSetAttribute(attn_kernel,
                         cudaFuncAttributeMaxDynamicSharedMemorySize, attn_smem);

    dim3 agrid(Ll / BM, Nn * Hh);
    attn_kernel<<<agrid, 256, attn_smem>>>(Q, K, V, M);

    dim3 pgrid(Ee / 64, (Nn * Ll) / 64);
    proj_kernel<<<pgrid, 256>>>(W, b, out);
}

// round 2
// speedup vs baseline: 2.6821x; 2.6821x over previous
#include <cuda_runtime.h>
#include <cstdint>

// Problem constants
#define Nn 2
#define Ll 2048
#define Ee 1024
#define Hh 16
#define Dd 64
#define SP 68          // smem row stride in 32-bit words (64 + 4 pad)

// Static device scratch (allocation-free per harness rules)
__device__ float    g_attn_out[(size_t)Nn * Ll * Ee];            // 16 MB
__device__ uint32_t g_mask_bits[(size_t)Nn * Ll * (Ll / 32)];    // 1 MB

// ---------------------------------------------------------------------------
// helpers
// ---------------------------------------------------------------------------
__device__ __forceinline__ uint32_t f2tf(float x) {
    uint32_t r;
    asm("cvt.rna.tf32.f32 %0, %1;" : "=r"(r) : "f"(x));
    return r;
}

// mma.sync m16n8k8 tf32: A row-major (4 regs), B col-major (2 regs), C f32 (4).
// A: a0=(r=gid,   k=tig)  a1=(r=gid+8, k=tig)  a2=(r=gid, k=tig+4) a3=(r=gid+8,k=tig+4)
// B: b0=(k=tig, n=gid)    b1=(k=tig+4, n=gid)
// C: c0=(r=gid, n=2tig) c1=(r=gid, n=2tig+1) c2=(r=gid+8, n=2tig) c3=(r=gid+8, n=2tig+1)
__device__ __forceinline__ void mma_tf32(float c[4],
                                         uint32_t a0, uint32_t a1, uint32_t a2, uint32_t a3,
                                         uint32_t b0, uint32_t b1) {
    asm volatile(
        "mma.sync.aligned.m16n8k8.row.col.f32.tf32.tf32.f32 "
        "{%0,%1,%2,%3},{%4,%5,%6,%7},{%8,%9},{%0,%1,%2,%3};"
        : "+f"(c[0]), "+f"(c[1]), "+f"(c[2]), "+f"(c[3])
        : "r"(a0), "r"(a1), "r"(a2), "r"(a3), "r"(b0), "r"(b1));
}

// ---------------------------------------------------------------------------
// Pack int32 mask -> bitmask. One warp produces one uint32 via ballot.
// ---------------------------------------------------------------------------
__global__ __launch_bounds__(256) void mask_pack(const int* __restrict__ M) {
    size_t gw = ((size_t)blockIdx.x * 256 + threadIdx.x) >> 5;
    int lane = threadIdx.x & 31;
    const size_t nwords = (size_t)Nn * Ll * (Ll / 32);
    if (gw < nwords) {
        int v = M[gw * 32 + lane];
        uint32_t bits = __ballot_sync(0xffffffffu, v != 0);
        if (lane == 0) g_mask_bits[gw] = bits;
    }
}

// ---------------------------------------------------------------------------
// Flash attention, tf32 mma. Grid (L/64, N*H), 128 threads = 4 warps.
// Warp w owns query rows [w*16, w*16+16) -> softmax is warp-private.
// ---------------------------------------------------------------------------
__global__ __launch_bounds__(128) void attn_mma(
    const float* __restrict__ Q, const float* __restrict__ K,
    const float* __restrict__ V)
{
    extern __shared__ uint32_t sm[];
    uint32_t* Qs = sm;              // [m 64][k 64] tf32 bits
    uint32_t* Ks = Qs + 64 * SP;    // [keyrow 64][k 64]
    uint32_t* Vt = Ks + 64 * SP;    // [d 64][keyrow 64]  (transposed!)
    uint32_t* Ss = Vt + 64 * SP;    // [m 64][keycol 64]  (P, warp-private rows)

    const int tid = threadIdx.x;
    const int lane = tid & 31;
    const int w = tid >> 5;
    const int gid = lane >> 2;      // 0..7
    const int tig = lane & 3;       // 0..3
    const int n = blockIdx.y >> 4;
    const int h = blockIdx.y & 15;
    const int q0 = blockIdx.x * 64;
    const int m0w = w * 16;

    // ---- Q tile -> smem (tf32 bits) ----
    const float* qb = Q + ((size_t)(n * Ll + q0)) * Ee + h * Dd;
    for (int idx = tid; idx < 64 * 16; idx += 128) {
        int r = idx >> 4, c4 = idx & 15;
        float4 v = *reinterpret_cast<const float4*>(qb + (size_t)r * Ee + c4 * 4);
        Qs[r * SP + c4 * 4 + 0] = f2tf(v.x);
        Qs[r * SP + c4 * 4 + 1] = f2tf(v.y);
        Qs[r * SP + c4 * 4 + 2] = f2tf(v.z);
        Qs[r * SP + c4 * 4 + 3] = f2tf(v.w);
    }

    float o[8][4];
    #pragma unroll
    for (int dt = 0; dt < 8; dt++)
        #pragma unroll
        for (int j = 0; j < 4; j++) o[dt][j] = 0.0f;
    float mr0 = -1e30f, mr1 = -1e30f, lr0 = 0.0f, lr1 = 0.0f;
    const float scale = 0.03125f;   // 1/sqrt(E)

    // mask bitword base for this warp's rows
    const uint32_t* mbase = g_mask_bits + ((size_t)n * Ll + q0 + m0w) * (Ll / 32);

    for (int kt = 0; kt < Ll / 64; kt++) {
        __syncthreads();   // prior PV reads of Ks/Vt done

        // ---- K (natural) + V (transposed) tiles ----
        const float* kb = K + ((size_t)(n * Ll + kt * 64)) * Ee + h * Dd;
        const float* vb = V + ((size_t)(n * Ll + kt * 64)) * Ee + h * Dd;
        for (int idx = tid; idx < 64 * 16; idx += 128) {
            int r = idx >> 4, c4 = idx & 15;
            float4 kv = *reinterpret_cast<const float4*>(kb + (size_t)r * Ee + c4 * 4);
            Ks[r * SP + c4 * 4 + 0] = f2tf(kv.x);
            Ks[r * SP + c4 * 4 + 1] = f2tf(kv.y);
            Ks[r * SP + c4 * 4 + 2] = f2tf(kv.z);
            Ks[r * SP + c4 * 4 + 3] = f2tf(kv.w);
            float4 vv = *reinterpret_cast<const float4*>(vb + (size_t)r * Ee + c4 * 4);
            Vt[(c4 * 4 + 0) * SP + r] = f2tf(vv.x);
            Vt[(c4 * 4 + 1) * SP + r] = f2tf(vv.y);
            Vt[(c4 * 4 + 2) * SP + r] = f2tf(vv.z);
            Vt[(c4 * 4 + 3) * SP + r] = f2tf(vv.w);
        }
        __syncthreads();

        // ---- S = Q K^T (warp: m16 x n64) ----
        float sf[8][4];
        #pragma unroll
        for (int nt = 0; nt < 8; nt++)
            #pragma unroll
            for (int j = 0; j < 4; j++) sf[nt][j] = 0.0f;

        #pragma unroll
        for (int kk = 0; kk < 8; kk++) {
            uint32_t a0 = Qs[(m0w + gid) * SP + kk * 8 + tig];
            uint32_t a1 = Qs[(m0w + gid + 8) * SP + kk * 8 + tig];
            uint32_t a2 = Qs[(m0w + gid) * SP + kk * 8 + tig + 4];
            uint32_t a3 = Qs[(m0w + gid + 8) * SP + kk * 8 + tig + 4];
            #pragma unroll
            for (int nt = 0; nt < 8; nt++) {
                uint32_t b0 = Ks[(nt * 8 + gid) * SP + kk * 8 + tig];
                uint32_t b1 = Ks[(nt * 8 + gid) * SP + kk * 8 + tig + 4];
                mma_tf32(sf[nt], a0, a1, a2, a3, b0, b1);
            }
        }

        // ---- mask + scale + row max (rows gid / gid+8, warp-private) ----
        uint32_t mw0a = mbase[(size_t)gid * (Ll / 32) + kt * 2];
        uint32_t mw0b = mbase[(size_t)gid * (Ll / 32) + kt * 2 + 1];
        uint32_t mw1a = mbase[(size_t)(gid + 8) * (Ll / 32) + kt * 2];
        uint32_t mw1b = mbase[(size_t)(gid + 8) * (Ll / 32) + kt * 2 + 1];
        float rmax0 = -1e30f, rmax1 = -1e30f;
        #pragma unroll
        for (int nt = 0; nt < 8; nt++) {
            int j0 = nt * 8 + 2 * tig, j1 = j0 + 1;
            uint32_t wr0 = (nt < 4) ? mw0a : mw0b;
            uint32_t wr1 = (nt < 4) ? mw1a : mw1b;
            sf[nt][0] = ((wr0 >> (j0 & 31)) & 1u) ? sf[nt][0] * scale : -1e20f;
            sf[nt][1] = ((wr0 >> (j1 & 31)) & 1u) ? sf[nt][1] * scale : -1e20f;
            sf[nt][2] = ((wr1 >> (j0 & 31)) & 1u) ? sf[nt][2] * scale : -1e20f;
            sf[nt][3] = ((wr1 >> (j1 & 31)) & 1u) ? sf[nt][3] * scale : -1e20f;
            rmax0 = fmaxf(rmax0, fmaxf(sf[nt][0], sf[nt][1]));
            rmax1 = fmaxf(rmax1, fmaxf(sf[nt][2], sf[nt][3]));
        }
        rmax0 = fmaxf(rmax0, __shfl_xor_sync(0xffffffffu, rmax0, 1));
        rmax0 = fmaxf(rmax0, __shfl_xor_sync(0xffffffffu, rmax0, 2));
        rmax1 = fmaxf(rmax1, __shfl_xor_sync(0xffffffffu, rmax1, 1));
        rmax1 = fmaxf(rmax1, __shfl_xor_sync(0xffffffffu, rmax1, 2));

        float mn0 = fmaxf(mr0, rmax0), mn1 = fmaxf(mr1, rmax1);
        float al0 = __expf(mr0 - mn0), al1 = __expf(mr1 - mn1);

        // ---- exp, row sums, write P (tf32) to warp-private Ss rows ----
        float ts0 = 0.0f, ts1 = 0.0f;
        #pragma unroll
        for (int nt = 0; nt < 8; nt++) {
            float p00 = __expf(sf[nt][0] - mn0);
            float p01 = __expf(sf[nt][1] - mn0);
            float p10 = __expf(sf[nt][2] - mn1);
            float p11 = __expf(sf[nt][3] - mn1);
            ts0 += p00 + p01;
            ts1 += p10 + p11;
            *reinterpret_cast<uint2*>(&Ss[(m0w + gid) * SP + nt * 8 + 2 * tig]) =
                make_uint2(f2tf(p00), f2tf(p01));
            *reinterpret_cast<uint2*>(&Ss[(m0w + gid + 8) * SP + nt * 8 + 2 * tig]) =
                make_uint2(f2tf(p10), f2tf(p11));
        }
        ts0 += __shfl_xor_sync(0xffffffffu, ts0, 1);
        ts0 += __shfl_xor_sync(0xffffffffu, ts0, 2);
        ts1 += __shfl_xor_sync(0xffffffffu, ts1, 1);
        ts1 += __shfl_xor_sync(0xffffffffu, ts1, 2);
        lr0 = lr0 * al0 + ts0;
        lr1 = lr1 * al1 + ts1;
        mr0 = mn0; mr1 = mn1;

        // ---- rescale O, then O += P V ----
        #pragma unroll
        for (int dt = 0; dt < 8; dt++) {
            o[dt][0] *= al0; o[dt][1] *= al0;
            o[dt][2] *= al1; o[dt][3] *= al1;
        }
        __syncwarp();
        #pragma unroll
        for (int kk = 0; kk < 8; kk++) {
            uint32_t a0 = Ss[(m0w + gid) * SP + kk * 8 + tig];
            uint32_t a1 = Ss[(m0w + gid + 8) * SP + kk * 8 + tig];
            uint32_t a2 = Ss[(m0w + gid) * SP + kk * 8 + tig + 4];
            uint32_t a3 = Ss[(m0w + gid + 8) * SP + kk * 8 + tig + 4];
            #pragma unroll
            for (int dt = 0; dt < 8; dt++) {
                uint32_t b0 = Vt[(dt * 8 + gid) * SP + kk * 8 + tig];
                uint32_t b1 = Vt[(dt * 8 + gid) * SP + kk * 8 + tig + 4];
                mma_tf32(o[dt], a0, a1, a2, a3, b0, b1);
            }
        }
    }

    // ---- normalize + write ----
    float inv0 = 1.0f / lr0, inv1 = 1.0f / lr1;
    float* ob0 = g_attn_out + ((size_t)(n * Ll + q0 + m0w + gid)) * Ee + h * Dd;
    float* ob1 = ob0 + (size_t)8 * Ee;
    #pragma unroll
    for (int dt = 0; dt < 8; dt++) {
        *reinterpret_cast<float2*>(ob0 + dt * 8 + 2 * tig) =
            make_float2(o[dt][0] * inv0, o[dt][1] * inv0);
        *reinterpret_cast<float2*>(ob1 + dt * 8 + 2 * tig) =
            make_float2(o[dt][2] * inv1, o[dt][3] * inv1);
    }
}

// ---------------------------------------------------------------------------
// Projection: out = X W^T + b, tf32 mma. Grid (E/64, M/64), 128 threads.
// ---------------------------------------------------------------------------
__global__ __launch_bounds__(128) void proj_mma(
    const float* __restrict__ Wm, const float* __restrict__ bias,
    float* __restrict__ out)
{
    __shared__ uint32_t Xs[64 * SP];
    __shared__ uint32_t Wsm[64 * SP];

    const int tid = threadIdx.x;
    const int lane = tid & 31;
    const int w = tid >> 5;
    const int gid = lane >> 2, tig = lane & 3;
    const int n0 = blockIdx.x * 64;
    const int m0 = blockIdx.y * 64;
    const int m0w = w * 16;

    float acc[8][4];
    #pragma unroll
    for (int nt = 0; nt < 8; nt++)
        #pragma unroll
        for (int j = 0; j < 4; j++) acc[nt][j] = 0.0f;

    for (int kc = 0; kc < Ee / 64; kc++) {
        __syncthreads();
        const float* xb = g_attn_out + (size_t)m0 * Ee + kc * 64;
        const float* wb = Wm + (size_t)n0 * Ee + kc * 64;
        for (int idx = tid; idx < 64 * 16; idx += 128) {
            int r = idx >> 4, c4 = idx & 15;
            float4 xv = *reinterpret_cast<const float4*>(xb + (size_t)r * Ee + c4 * 4);
            Xs[r * SP + c4 * 4 + 0] = f2tf(xv.x);
            Xs[r * SP + c4 * 4 + 1] = f2tf(xv.y);
            Xs[r * SP + c4 * 4 + 2] = f2tf(xv.z);
            Xs[r * SP + c4 * 4 + 3] = f2tf(xv.w);
            float4 wv = *reinterpret_cast<const float4*>(wb + (size_t)r * Ee + c4 * 4);
            Wsm[r * SP + c4 * 4 + 0] = f2tf(wv.x);
            Wsm[r * SP + c4 * 4 + 1] = f2tf(wv.y);
            Wsm[r * SP + c4 * 4 + 2] = f2tf(wv.z);
            Wsm[r * SP + c4 * 4 + 3] = f2tf(wv.w);
        }
        __syncthreads();

        #pragma unroll
        for (int kk = 0; kk < 8; kk++) {
            uint32_t a0 = Xs[(m0w + gid) * SP + kk * 8 + tig];
            uint32_t a1 = Xs[(m0w + gid + 8) * SP + kk * 8 + tig];
            uint32_t a2 = Xs[(m0w + gid) * SP + kk * 8 + tig + 4];
            uint32_t a3 = Xs[(m0w + gid + 8) * SP + kk * 8 + tig + 4];
            #pragma unroll
            for (int nt = 0; nt < 8; nt++) {
                uint32_t b0 = Wsm[(nt * 8 + gid) * SP + kk * 8 + tig];
                uint32_t b1 = Wsm[(nt * 8 + gid) * SP + kk * 8 + tig + 4];
                mma_tf32(acc[nt], a0, a1, a2, a3, b0, b1);
            }
        }
    }

    float* ob0 = out + (size_t)(m0 + m0w + gid) * Ee + n0;
    float* ob1 = ob0 + (size_t)8 * Ee;
    #pragma unroll
    for (int nt = 0; nt < 8; nt++) {
        float2 bv = *reinterpret_cast<const float2*>(bias + n0 + nt * 8 + 2 * tig);
        *reinterpret_cast<float2*>(ob0 + nt * 8 + 2 * tig) =
            make_float2(acc[nt][0] + bv.x, acc[nt][1] + bv.y);
        *reinterpret_cast<float2*>(ob1 + nt * 8 + 2 * tig) =
            make_float2(acc[nt][2] + bv.x, acc[nt][3] + bv.y);
    }
}

extern "C" void kernel_launch(void* const* d_in, const int* in_sizes, int n_in,
                              void* d_out, int out_size)
{
    const float* Q = (const float*)d_in[0];
    const float* K = (const float*)d_in[1];
    const float* V = (const float*)d_in[2];
    const int*   M = (const int*)d_in[3];
    const float* W = (const float*)d_in[4];
    const float* b = (const float*)d_in[5];
    float* out = (float*)d_out;

    // 1) pack mask to bits (one warp per output word)
    {
        size_t nwords = (size_t)Nn * Ll * (Ll / 32);
        int blocks = (int)((nwords * 32 + 255) / 256);
        mask_pack<<<blocks, 256>>>(M);
    }

    // 2) fused flash attention (tf32 mma)
    {
        const int smem = 4 * 64 * SP * (int)sizeof(uint32_t);  // 69632 B
        cudaFuncSetAttribute(attn_mma,
                             cudaFuncAttributeMaxDynamicSharedMemorySize, smem);
        dim3 grid(Ll / 64, Nn * Hh);
        attn_mma<<<grid, 128, smem>>>(Q, K, V);
    }

    // 3) output projection (tf32 mma)
    {
        dim3 grid(Ee / 64, (Nn * Ll) / 64);
        proj_mma<<<grid, 128>>>(W, b, out);
    }
}

// round 4
// speedup vs baseline: 7.1458x; 2.6643x over previous
#include <cuda_runtime.h>
#include <cuda_fp16.h>
#include <cstdint>

// Problem constants
#define Nn 2
#define Ll 2048
#define Ee 1024
#define Hh 16
#define Dd 64
#define NT (Ll / 64)      // 32 key tiles
#define SQH 72            // smem row stride in halves (144 B)

// Static device scratch (allocation-free per harness rules)
__device__ __align__(16) __half   g_qh[(size_t)Nn * Ll * Ee];        // Q * 1/32, fp16
__device__ __align__(16) __half   g_kh[(size_t)Nn * Ll * Ee];        // K fp16
__device__ __align__(16) __half   g_vt[(size_t)Nn * Hh * Dd * Ll];   // V fp16 transposed [n][h][d][l]
__device__ __align__(16) __half   g_attn_half[(size_t)Nn * Ll * Ee]; // attention out fp16
__device__ __align__(16) __half   g_wh[(size_t)Ee * Ee];             // W fp16
__device__ __align__(16) uint32_t g_mask_bits[(size_t)Nn * Ll * (Ll / 32)];

// ---------------------------------------------------------------------------
// helpers
// ---------------------------------------------------------------------------
__device__ __forceinline__ uint32_t smem_u32(const void* p) {
    uint32_t a;
    asm("{ .reg .u64 t; cvta.to.shared.u64 t, %1; cvt.u32.u64 %0, t; }"
        : "=r"(a) : "l"(p));
    return a;
}

__device__ __forceinline__ void ldmx4(uint32_t& r0, uint32_t& r1,
                                      uint32_t& r2, uint32_t& r3, uint32_t addr) {
    asm volatile("ldmatrix.sync.aligned.m8n8.x4.shared.b16 {%0,%1,%2,%3}, [%4];"
                 : "=r"(r0), "=r"(r1), "=r"(r2), "=r"(r3) : "r"(addr));
}

// mma m16n8k16 row.col f32.f16.f16.f32
// A: a0=(gid,2tig..+1 | k0:8) a1=(gid+8, k0:8) a2=(gid, k8:16) a3=(gid+8, k8:16)
// B: b0=(k0:8 pair 2tig, n=gid) b1=(k8:16, n=gid)
// C: c0=(gid, 2tig) c1=(gid, 2tig+1) c2=(gid+8, 2tig) c3=(gid+8, 2tig+1)
__device__ __forceinline__ void mma16816(float c[4], uint32_t a0, uint32_t a1,
                                         uint32_t a2, uint32_t a3,
                                         uint32_t b0, uint32_t b1) {
    asm volatile(
        "mma.sync.aligned.m16n8k16.row.col.f32.f16.f16.f32 "
        "{%0,%1,%2,%3},{%4,%5,%6,%7},{%8,%9},{%0,%1,%2,%3};"
        : "+f"(c[0]), "+f"(c[1]), "+f"(c[2]), "+f"(c[3])
        : "r"(a0), "r"(a1), "r"(a2), "r"(a3), "r"(b0), "r"(b1));
}

#define CPA16(dst, src) \
    asm volatile("cp.async.cg.shared.global [%0], [%1], 16;" :: "r"(dst), "l"(src))
#define CPA_COMMIT() asm volatile("cp.async.commit_group;" ::: "memory")
#define CPA_WAIT1()  asm volatile("cp.async.wait_group 1;" ::: "memory")

__device__ __forceinline__ uint32_t h2u(__half2 h) { return *reinterpret_cast<uint32_t*>(&h); }

// ===========================================================================
// Prepass 1: convert Q (scaled 1/32), K, W to fp16 (float4-vectorized)
// ===========================================================================
#define EQ ((size_t)Nn * Ll * Ee)
#define EW ((size_t)Ee * Ee)
__global__ __launch_bounds__(256) void conv_qkw(
    const float* __restrict__ Q, const float* __restrict__ K,
    const float* __restrict__ W)
{
    const size_t q4 = EQ / 4, k4 = EQ / 4, w4 = EW / 4;
    const size_t tot = q4 + k4 + w4;
    for (size_t i = (size_t)blockIdx.x * 256 + threadIdx.x; i < tot;
         i += (size_t)gridDim.x * 256) {
        const float* src; __half* dst; float sc; size_t j;
        if (i < q4)            { src = Q; dst = g_qh; sc = 0.03125f; j = i; }
        else if (i < q4 + k4)  { src = K; dst = g_kh; sc = 1.0f; j = i - q4; }
        else                   { src = W; dst = g_wh; sc = 1.0f; j = i - q4 - k4; }
        float4 v = reinterpret_cast<const float4*>(src)[j];
        __half2 h0 = __floats2half2_rn(v.x * sc, v.y * sc);
        __half2 h1 = __floats2half2_rn(v.z * sc, v.w * sc);
        reinterpret_cast<uint2*>(dst)[j] = make_uint2(h2u(h0), h2u(h1));
    }
}

// ===========================================================================
// Prepass 2: V -> fp16 transposed g_vt[n][h][d][l]. Grid (L/64, N*H), 256 thr.
// ===========================================================================
__global__ __launch_bounds__(256) void v_transpose(const float* __restrict__ V) {
    __shared__ float sm[64][65];
    const int l0 = blockIdx.x * 64;
    const int n  = blockIdx.y >> 4;
    const int h  = blockIdx.y & 15;
    const int tid = threadIdx.x;
    // read 64 rows x 64 floats (coalesced float4)
    const float* vb = V + ((size_t)(n * Ll + l0)) * Ee + h * Dd;
    for (int idx = tid; idx < 64 * 16; idx += 256) {
        int r = idx >> 4, c4 = idx & 15;
        float4 v = *reinterpret_cast<const float4*>(vb + (size_t)r * Ee + c4 * 4);
        sm[r][c4 * 4 + 0] = v.x; sm[r][c4 * 4 + 1] = v.y;
        sm[r][c4 * 4 + 2] = v.z; sm[r][c4 * 4 + 3] = v.w;
    }
    __syncthreads();
    // write rows d: 64 halves each (coalesced)
    const int d = tid >> 2;
    const int lb = (tid & 3) * 16;
    __half* ob = g_vt + (((size_t)(n * Hh + h) * Dd + d)) * Ll + l0 + lb;
    uint32_t pk[8];
    #pragma unroll
    for (int i = 0; i < 8; i++)
        pk[i] = h2u(__floats2half2_rn(sm[lb + 2 * i][d], sm[lb + 2 * i + 1][d]));
    *reinterpret_cast<uint4*>(ob)     = make_uint4(pk[0], pk[1], pk[2], pk[3]);
    *reinterpret_cast<uint4*>(ob + 8) = make_uint4(pk[4], pk[5], pk[6], pk[7]);
}

// ===========================================================================
// Prepass 3: mask -> bitmask, 8 words per warp (MLP=8)
// ===========================================================================
__global__ __launch_bounds__(256) void mask_pack(const int* __restrict__ M) {
    const size_t nwords = (size_t)Nn * Ll * (Ll / 32);
    size_t wbase = (((size_t)blockIdx.x * 256 + threadIdx.x) >> 5) * 8;
    int lane = threadIdx.x & 31;
    if (wbase >= nwords) return;
    int v[8];
    #pragma unroll
    for (int j = 0; j < 8; j++) v[j] = M[(wbase + j) * 32 + lane];
    uint32_t b[8];
    #pragma unroll
    for (int j = 0; j < 8; j++) b[j] = __ballot_sync(0xffffffffu, v[j] != 0);
    if (lane == 0) {
        *reinterpret_cast<uint4*>(&g_mask_bits[wbase])     = make_uint4(b[0], b[1], b[2], b[3]);
        *reinterpret_cast<uint4*>(&g_mask_bits[wbase + 4]) = make_uint4(b[4], b[5], b[6], b[7]);
    }
}

// ===========================================================================
// Flash attention, fp16 mma.sync + ldmatrix, no max-shift, register-direct P.
// Grid (L/128, N*H) = (16, 32), 256 threads = 8 warps (16 q-rows each).
// Double-buffered K/Vt tiles via cp.async.
// ===========================================================================
#define SMQ_OFF 0
#define SMK_OFF (128 * SQH * 2)              // 18432
#define SMV_OFF (SMK_OFF + 64 * SQH * 2)     // +9216
#define STAGE   (2 * 64 * SQH * 2)           // 18432 per stage (K+V)
#define SM_ATT_TOTAL (SMK_OFF + 2 * STAGE)   // 55296 B

__global__ __launch_bounds__(256) void attn_hmma(
    const int* __restrict__ dummy)
{
    extern __shared__ __align__(16) char smem[];
    const uint32_t sb = smem_u32(smem);
    const int tid = threadIdx.x;
    const int lane = tid & 31;
    const int wid = tid >> 5;
    const int gid = lane >> 2, tig = lane & 3;
    const int n = blockIdx.y >> 4;
    const int h = blockIdx.y & 15;
    const int q0 = blockIdx.x * 128;
    const int m0w = wid * 16;

    // ---- preload Q (128 rows) + tile 0 (K/V) via cp.async ----
    {
        const __half* qb = g_qh + ((size_t)(n * Ll + q0)) * Ee + h * Dd;
        #pragma unroll
        for (int i = 0; i < 4; i++) {
            int idx = tid + i * 256;                 // 1024 chunks
            int r = idx >> 3, c = idx & 7;
            CPA16(sb + SMQ_OFF + r * 144 + c * 16, qb + (size_t)r * Ee + c * 8);
        }
        const __half* kb = g_kh + ((size_t)(n * Ll)) * Ee + h * Dd;
        const __half* vb = g_vt + ((size_t)(n * Hh + h) * Dd) * Ll;
        #pragma unroll
        for (int i = 0; i < 2; i++) {
            int idx = tid + i * 256;                 // 512 chunks each
            int r = idx >> 3, c = idx & 7;
            CPA16(sb + SMK_OFF + r * 144 + c * 16, kb + (size_t)r * Ee + c * 8);
            CPA16(sb + SMV_OFF + r * 144 + c * 16, vb + (size_t)r * Ll + c * 8);
        }
        CPA_COMMIT();
    }

    float O[8][4];
    #pragma unroll
    for (int t = 0; t < 8; t++)
        #pragma unroll
        for (int j = 0; j < 4; j++) O[t][j] = 0.0f;
    float lsum0 = 0.0f, lsum1 = 0.0f;

    // per-lane ldmatrix address components
    const uint32_t aQrow = sb + SMQ_OFF + (m0w + (lane & 15)) * 144 + ((lane >> 4) << 4);
    const uint32_t bRowSel = (((lane >> 4) & 1) << 3) + (lane & 7);   // row within 16
    const uint32_t bKhi    = ((lane >> 3) & 1) << 4;                  // +16B if k-high

    const uint32_t* mb0 = g_mask_bits + ((size_t)(n * Ll + q0 + m0w + gid)) * (Ll / 32);
    const uint32_t* mb1 = mb0 + (size_t)8 * (Ll / 32);

    for (int kt = 0; kt < NT; kt++) {
        // prefetch next tile into other stage
        if (kt + 1 < NT) {
            const __half* kb = g_kh + ((size_t)(n * Ll + (kt + 1) * 64)) * Ee + h * Dd;
            const __half* vb = g_vt + ((size_t)(n * Hh + h) * Dd) * Ll + (kt + 1) * 64;
            uint32_t st = sb + SMK_OFF + ((kt + 1) & 1) * STAGE;
            #pragma unroll
            for (int i = 0; i < 2; i++) {
                int idx = tid + i * 256;
                int r = idx >> 3, c = idx & 7;
                CPA16(st + r * 144 + c * 16, kb + (size_t)r * Ee + c * 8);
                CPA16(st + (64 * SQH * 2) + r * 144 + c * 16, vb + (size_t)r * Ll + c * 8);
            }
        }
        CPA_COMMIT();
        CPA_WAIT1();
        __syncthreads();

        const uint32_t kbase = sb + SMK_OFF + (kt & 1) * STAGE;
        const uint32_t vbase = kbase + 64 * SQH * 2;

        // mask words (prefetch before QK)
        uint32_t mw0a = mb0[kt * 2], mw0b = mb0[kt * 2 + 1];
        uint32_t mw1a = mb1[kt * 2], mw1b = mb1[kt * 2 + 1];

        // ---- S = Q K^T : warp m16 x n64 ----
        float S[8][4];
        #pragma unroll
        for (int t = 0; t < 8; t++)
            #pragma unroll
            for (int j = 0; j < 4; j++) S[t][j] = 0.0f;

        #pragma unroll
        for (int kc = 0; kc < 4; kc++) {
            uint32_t a0, a1, a2, a3;
            ldmx4(a0, a1, a2, a3, aQrow + kc * 32);
            #pragma unroll
            for (int j = 0; j < 4; j++) {
                uint32_t b0, b1, b2, b3;
                ldmx4(b0, b1, b2, b3,
                      kbase + (j * 16 + bRowSel) * 144 + kc * 32 + bKhi);
                mma16816(S[2 * j],     a0, a1, a2, a3, b0, b1);
                mma16816(S[2 * j + 1], a0, a1, a2, a3, b2, b3);
            }
        }

        // ---- P = mask ? exp(S) : 0 ; pack to fp16 A-fragments in regs ----
        uint32_t Ap0[8], Ap1[8];   // rows gid / gid+8
        #pragma unroll
        for (int t = 0; t < 8; t++) {
            int j0 = t * 8 + 2 * tig;
            uint32_t w0 = (t < 4) ? mw0a : mw0b;
            uint32_t w1 = (t < 4) ? mw1a : mw1b;
            float p00 = ((w0 >> (j0 & 31)) & 1u)        ? __expf(S[t][0]) : 0.0f;
            float p01 = ((w0 >> ((j0 + 1) & 31)) & 1u)  ? __expf(S[t][1]) : 0.0f;
            float p10 = ((w1 >> (j0 & 31)) & 1u)        ? __expf(S[t][2]) : 0.0f;
            float p11 = ((w1 >> ((j0 + 1) & 31)) & 1u)  ? __expf(S[t][3]) : 0.0f;
            lsum0 += p00 + p01;
            lsum1 += p10 + p11;
            Ap0[t] = h2u(__floats2half2_rn(p00, p01));
            Ap1[t] = h2u(__floats2half2_rn(p10, p11));
        }

        // ---- O += P V (A direct from registers, B = Vt via ldmatrix) ----
        #pragma unroll
        for (int kc = 0; kc < 4; kc++) {
            uint32_t a0 = Ap0[2 * kc], a1 = Ap1[2 * kc];
            uint32_t a2 = Ap0[2 * kc + 1], a3 = Ap1[2 * kc + 1];
            #pragma unroll
            for (int j = 0; j < 4; j++) {
                uint32_t b0, b1, b2, b3;
                ldmx4(b0, b1, b2, b3,
                      vbase + (j * 16 + bRowSel) * 144 + kc * 32 + bKhi);
                mma16816(O[2 * j],     a0, a1, a2, a3, b0, b1);
                mma16816(O[2 * j + 1], a0, a1, a2, a3, b2, b3);
            }
        }
        __syncthreads();   // done reading this stage before it's overwritten
    }

    // ---- reduce row sums over the 4 tig lanes, normalize, store fp16 ----
    lsum0 += __shfl_xor_sync(0xffffffffu, lsum0, 1);
    lsum0 += __shfl_xor_sync(0xffffffffu, lsum0, 2);
    lsum1 += __shfl_xor_sync(0xffffffffu, lsum1, 1);
    lsum1 += __shfl_xor_sync(0xffffffffu, lsum1, 2);
    float inv0 = 1.0f / lsum0, inv1 = 1.0f / lsum1;

    __half* ob0 = g_attn_half + ((size_t)(n * Ll + q0 + m0w + gid)) * Ee + h * Dd;
    __half* ob1 = ob0 + (size_t)8 * Ee;
    #pragma unroll
    for (int t = 0; t < 8; t++) {
        *reinterpret_cast<uint32_t*>(ob0 + t * 8 + 2 * tig) =
            h2u(__floats2half2_rn(O[t][0] * inv0, O[t][1] * inv0));
        *reinterpret_cast<uint32_t*>(ob1 + t * 8 + 2 * tig) =
            h2u(__floats2half2_rn(O[t][2] * inv1, O[t][3] * inv1));
    }
}

// ===========================================================================
// Projection: out = X W^T + b. fp16 mma, CTA tile 128x128, K-chunks of 64,
// double-buffered. Grid (E/128, M/128) = (8, 32), 256 threads.
// ===========================================================================
#define PJ_STAGE (2 * 128 * SQH * 2)         // X + W per stage = 36864
#define PJ_TOTAL (2 * PJ_STAGE)              // 73728 B

__global__ __launch_bounds__(256) void proj_hmma(
    const float* __restrict__ bias, float* __restrict__ out)
{
    extern __shared__ __align__(16) char smem[];
    const uint32_t sb = smem_u32(smem);
    const int tid = threadIdx.x;
    const int lane = tid & 31;
    const int wid = tid >> 5;
    const int gid = lane >> 2, tig = lane & 3;
    const int n0 = blockIdx.x * 128;
    const int m0 = blockIdx.y * 128;
    const int m0w = wid * 16;

    const uint32_t bRowSel = (((lane >> 4) & 1) << 3) + (lane & 7);
    const uint32_t bKhi    = ((lane >> 3) & 1) << 4;

    auto issue = [&](int kc) {
        const __half* xb = g_attn_half + (size_t)m0 * Ee + kc * 64;
        const __half* wb = g_wh + (size_t)n0 * Ee + kc * 64;
        uint32_t st = sb + (kc & 1) * PJ_STAGE;
        #pragma unroll
        for (int i = 0; i < 4; i++) {
            int idx = tid + i * 256;                 // 1024 chunks each
            int r = idx >> 3, c = idx & 7;
            CPA16(st + r * 144 + c * 16, xb + (size_t)r * Ee + c * 8);
            CPA16(st + 128 * SQH * 2 + r * 144 + c * 16, wb + (size_t)r * Ee + c * 8);
        }
    };

    float C[16][4];
    #pragma unroll
    for (int t = 0; t < 16; t++)
        #pragma unroll
        for (int j = 0; j < 4; j++) C[t][j] = 0.0f;

    issue(0);
    CPA_COMMIT();

    for (int kc = 0; kc < Ee / 64; kc++) {
        if (kc + 1 < Ee / 64) issue(kc + 1);
        CPA_COMMIT();
        CPA_WAIT1();
        __syncthreads();

        const uint32_t xbase = sb + (kc & 1) * PJ_STAGE;
        const uint32_t wbase = xbase + 128 * SQH * 2;
        const uint32_t aXrow = xbase + (m0w + (lane & 15)) * 144 + ((lane >> 4) << 4);

        #pragma unroll
        for (int k4 = 0; k4 < 4; k4++) {
            uint32_t a0, a1, a2, a3;
            ldmx4(a0, a1, a2, a3, aXrow + k4 * 32);
            #pragma unroll
            for (int j = 0; j < 8; j++) {
                uint32_t b0, b1, b2, b3;
                ldmx4(b0, b1, b2, b3,
                      wbase + (j * 16 + bRowSel) * 144 + k4 * 32 + bKhi);
                mma16816(C[2 * j],     a0, a1, a2, a3, b0, b1);
                mma16816(C[2 * j + 1], a0, a1, a2, a3, b2, b3);
            }
        }
        __syncthreads();
    }

    float* ob0 = out + (size_t)(m0 + m0w + gid) * Ee + n0;
    float* ob1 = ob0 + (size_t)8 * Ee;
    #pragma unroll
    for (int t = 0; t < 16; t++) {
        float2 bv = *reinterpret_cast<const float2*>(bias + n0 + t * 8 + 2 * tig);
        *reinterpret_cast<float2*>(ob0 + t * 8 + 2 * tig) =
            make_float2(C[t][0] + bv.x, C[t][1] + bv.y);
        *reinterpret_cast<float2*>(ob1 + t * 8 + 2 * tig) =
            make_float2(C[t][2] + bv.x, C[t][3] + bv.y);
    }
}

// ===========================================================================
extern "C" void kernel_launch(void* const* d_in, const int* in_sizes, int n_in,
                              void* d_out, int out_size)
{
    const float* Q = (const float*)d_in[0];
    const float* K = (const float*)d_in[1];
    const float* V = (const float*)d_in[2];
    const int*   M = (const int*)d_in[3];
    const float* W = (const float*)d_in[4];
    const float* b = (const float*)d_in[5];
    float* out = (float*)d_out;

    // prepass: fp16 conversions + V transpose + mask bitpack
    conv_qkw<<<2048, 256>>>(Q, K, W);
    {
        dim3 g(Ll / 64, Nn * Hh);
        v_transpose<<<g, 256>>>(V);
    }
    {
        size_t nwords = (size_t)Nn * Ll * (Ll / 32);
        size_t nwarps = (nwords + 7) / 8;
        mask_pack<<<(int)((nwarps + 7) / 8), 256>>>(M);
    }

    // attention
    cudaFuncSetAttribute(attn_hmma,
                         cudaFuncAttributeMaxDynamicSharedMemorySize, SM_ATT_TOTAL);
    {
        dim3 g(Ll / 128, Nn * Hh);
        attn_hmma<<<g, 256, SM_ATT_TOTAL>>>(M);
    }

    // projection
    cudaFuncSetAttribute(proj_hmma,
                         cudaFuncAttributeMaxDynamicSharedMemorySize, PJ_TOTAL);
    {
        dim3 g(Ee / 128, (Nn * Ll) / 128);
        proj_hmma<<<g, 256, PJ_TOTAL>>>(b, out);
    }
}

// round 6
// speedup vs baseline: 7.9720x; 1.1156x over previous
#include <cuda_runtime.h>
#include <cuda_fp16.h>
#include <cstdint>

// Problem constants
#define Nn 2
#define Ll 2048
#define Ee 1024
#define Hh 16
#define Dd 64
#define NT (Ll / 64)      // 32 key tiles
#define SQH 72            // smem row stride in halves (144 B)

// Static device scratch (allocation-free per harness rules)
__device__ __align__(16) __half   g_qh[(size_t)Nn * Ll * Ee];        // Q * log2e/32
__device__ __align__(16) __half   g_kh[(size_t)Nn * Ll * Ee];        // K fp16
__device__ __align__(16) __half   g_vt[(size_t)Nn * Hh * Dd * Ll];   // V fp16 transposed [n][h][d][l]
__device__ __align__(16) __half   g_attn_half[(size_t)Nn * Ll * Ee]; // attention out fp16
__device__ __align__(16) __half   g_wh[(size_t)Ee * Ee];             // W fp16
__device__ __align__(16) uint32_t g_mask_bits[(size_t)Nn * Ll * (Ll / 32)];

// ---------------------------------------------------------------------------
// helpers
// ---------------------------------------------------------------------------
__device__ __forceinline__ uint32_t smem_u32(const void* p) {
    uint32_t a;
    asm("{ .reg .u64 t; cvta.to.shared.u64 t, %1; cvt.u32.u64 %0, t; }"
        : "=r"(a) : "l"(p));
    return a;
}

__device__ __forceinline__ void ldmx4(uint32_t& r0, uint32_t& r1,
                                      uint32_t& r2, uint32_t& r3, uint32_t addr) {
    asm volatile("ldmatrix.sync.aligned.m8n8.x4.shared.b16 {%0,%1,%2,%3}, [%4];"
                 : "=r"(r0), "=r"(r1), "=r"(r2), "=r"(r3) : "r"(addr));
}

__device__ __forceinline__ void mma16816(float c[4], uint32_t a0, uint32_t a1,
                                         uint32_t a2, uint32_t a3,
                                         uint32_t b0, uint32_t b1) {
    asm volatile(
        "mma.sync.aligned.m16n8k16.row.col.f32.f16.f16.f32 "
        "{%0,%1,%2,%3},{%4,%5,%6,%7},{%8,%9},{%0,%1,%2,%3};"
        : "+f"(c[0]), "+f"(c[1]), "+f"(c[2]), "+f"(c[3])
        : "r"(a0), "r"(a1), "r"(a2), "r"(a3), "r"(b0), "r"(b1));
}

// pack 2 floats to half2 bits: lo -> low half, hi -> high half
// (PTX cvt.rn.f16x2.f32 d, a, b puts FIRST source in the UPPER half)
__device__ __forceinline__ uint32_t cvt_h2(float lo, float hi) {
    uint32_t d;
    asm("cvt.rn.f16x2.f32 %0, %1, %2;" : "=r"(d) : "f"(hi), "f"(lo));
    return d;
}
// 2^x on both halves
__device__ __forceinline__ uint32_t ex2_h2(uint32_t s) {
    uint32_t d;
    asm("ex2.approx.f16x2 %0, %1;" : "=r"(d) : "r"(s));
    return d;
}

#define CPA16(dst, src) \
    asm volatile("cp.async.cg.shared.global [%0], [%1], 16;" :: "r"(dst), "l"(src))
#define CPA_COMMIT() asm volatile("cp.async.commit_group;" ::: "memory")
#define CPA_WAIT1()  asm volatile("cp.async.wait_group 1;" ::: "memory")

__device__ __forceinline__ uint32_t h2u(__half2 h) { return *reinterpret_cast<uint32_t*>(&h); }

// ===========================================================================
// Prepass 1: convert Q (scaled log2e/32), K, W to fp16
// ===========================================================================
#define EQ ((size_t)Nn * Ll * Ee)
#define EW ((size_t)Ee * Ee)
__global__ __launch_bounds__(256) void conv_qkw(
    const float* __restrict__ Q, const float* __restrict__ K,
    const float* __restrict__ W)
{
    const size_t q4 = EQ / 4, k4 = EQ / 4, w4 = EW / 4;
    const size_t tot = q4 + k4 + w4;
    const float QSC = 0.045084437f;   // log2(e)/32
    for (size_t i = (size_t)blockIdx.x * 256 + threadIdx.x; i < tot;
         i += (size_t)gridDim.x * 256) {
        const float* src; __half* dst; float sc; size_t j;
        if (i < q4)            { src = Q; dst = g_qh; sc = QSC; j = i; }
        else if (i < q4 + k4)  { src = K; dst = g_kh; sc = 1.0f; j = i - q4; }
        else                   { src = W; dst = g_wh; sc = 1.0f; j = i - q4 - k4; }
        float4 v = reinterpret_cast<const float4*>(src)[j];
        __half2 h0 = __floats2half2_rn(v.x * sc, v.y * sc);
        __half2 h1 = __floats2half2_rn(v.z * sc, v.w * sc);
        reinterpret_cast<uint2*>(dst)[j] = make_uint2(h2u(h0), h2u(h1));
    }
}

// ===========================================================================
// Prepass 2: V -> fp16 transposed g_vt[n][h][d][l]
// ===========================================================================
__global__ __launch_bounds__(256) void v_transpose(const float* __restrict__ V) {
    __shared__ float sm[64][65];
    const int l0 = blockIdx.x * 64;
    const int n  = blockIdx.y >> 4;
    const int h  = blockIdx.y & 15;
    const int tid = threadIdx.x;
    const float* vb = V + ((size_t)(n * Ll + l0)) * Ee + h * Dd;
    for (int idx = tid; idx < 64 * 16; idx += 256) {
        int r = idx >> 4, c4 = idx & 15;
        float4 v = *reinterpret_cast<const float4*>(vb + (size_t)r * Ee + c4 * 4);
        sm[r][c4 * 4 + 0] = v.x; sm[r][c4 * 4 + 1] = v.y;
        sm[r][c4 * 4 + 2] = v.z; sm[r][c4 * 4 + 3] = v.w;
    }
    __syncthreads();
    const int d = tid >> 2;
    const int lb = (tid & 3) * 16;
    __half* ob = g_vt + (((size_t)(n * Hh + h) * Dd + d)) * Ll + l0 + lb;
    uint32_t pk[8];
    #pragma unroll
    for (int i = 0; i < 8; i++)
        pk[i] = h2u(__floats2half2_rn(sm[lb + 2 * i][d], sm[lb + 2 * i + 1][d]));
    *reinterpret_cast<uint4*>(ob)     = make_uint4(pk[0], pk[1], pk[2], pk[3]);
    *reinterpret_cast<uint4*>(ob + 8) = make_uint4(pk[4], pk[5], pk[6], pk[7]);
}

// ===========================================================================
// Prepass 3: mask -> bitmask, 8 words per warp
// ===========================================================================
__global__ __launch_bounds__(256) void mask_pack(const int* __restrict__ M) {
    const size_t nwords = (size_t)Nn * Ll * (Ll / 32);
    size_t wbase = (((size_t)blockIdx.x * 256 + threadIdx.x) >> 5) * 8;
    int lane = threadIdx.x & 31;
    if (wbase >= nwords) return;
    int v[8];
    #pragma unroll
    for (int j = 0; j < 8; j++) v[j] = M[(wbase + j) * 32 + lane];
    uint32_t b[8];
    #pragma unroll
    for (int j = 0; j < 8; j++) b[j] = __ballot_sync(0xffffffffu, v[j] != 0);
    if (lane == 0) {
        *reinterpret_cast<uint4*>(&g_mask_bits[wbase])     = make_uint4(b[0], b[1], b[2], b[3]);
        *reinterpret_cast<uint4*>(&g_mask_bits[wbase + 4]) = make_uint4(b[4], b[5], b[6], b[7]);
    }
}

// ===========================================================================
// Flash attention. fp16 mma + ldmatrix; softmax via packed fp16x2 ex2;
// mask via plain ISETP/SEL half-masks; row-sum via ones-row tensor mma.
// Grid (L/128, N*H) = (16, 32), 256 threads = 8 warps (16 q-rows each).
// ===========================================================================
#define SMQ_OFF 0
#define SMK_OFF (128 * SQH * 2)              // 18432
#define VOFF    (64 * SQH * 2)               // 9216 (V within stage)
#define STAGE   (VOFF + 80 * SQH * 2)        // K 64 rows + V 80 rows = 20736
#define SM_ATT_TOTAL (SMK_OFF + 2 * STAGE)   // 59904 B

__global__ __launch_bounds__(256) void attn_hmma(
    const int* __restrict__ dummy)
{
    extern __shared__ __align__(16) char smem[];
    const uint32_t sb = smem_u32(smem);
    const int tid = threadIdx.x;
    const int lane = tid & 31;
    const int wid = tid >> 5;
    const int gid = lane >> 2, tig = lane & 3;
    const int n = blockIdx.y >> 4;
    const int h = blockIdx.y & 15;
    const int q0 = blockIdx.x * 128;
    const int m0w = wid * 16;

    // ---- init ones-region of both V stages (rows 64..79; row 64 = 1.0) ----
    for (int i = tid; i < 2 * 16 * 36; i += 256) {
        int st = i / (16 * 36), rem = i % (16 * 36);
        int r = rem / 36, c = rem % 36;
        uint32_t val = (r == 0 && c < 32) ? 0x3C003C00u : 0u;
        *reinterpret_cast<uint32_t*>(smem + SMK_OFF + st * STAGE + VOFF +
                                     (64 + r) * 144 + c * 4) = val;
    }

    // ---- preload Q (128 rows) + tile 0 (K/V) via cp.async ----
    {
        const __half* qb = g_qh + ((size_t)(n * Ll + q0)) * Ee + h * Dd;
        #pragma unroll
        for (int i = 0; i < 4; i++) {
            int idx = tid + i * 256;
            int r = idx >> 3, c = idx & 7;
            CPA16(sb + SMQ_OFF + r * 144 + c * 16, qb + (size_t)r * Ee + c * 8);
        }
        const __half* kb = g_kh + ((size_t)(n * Ll)) * Ee + h * Dd;
        const __half* vb = g_vt + ((size_t)(n * Hh + h) * Dd) * Ll;
        #pragma unroll
        for (int i = 0; i < 2; i++) {
            int idx = tid + i * 256;
            int r = idx >> 3, c = idx & 7;
            CPA16(sb + SMK_OFF + r * 144 + c * 16, kb + (size_t)r * Ee + c * 8);
            CPA16(sb + SMK_OFF + VOFF + r * 144 + c * 16, vb + (size_t)r * Ll + c * 8);
        }
        CPA_COMMIT();
    }

    float O[8][4];
    #pragma unroll
    for (int t = 0; t < 8; t++)
        #pragma unroll
        for (int j = 0; j < 4; j++) O[t][j] = 0.0f;
    float Cl[4] = {0.0f, 0.0f, 0.0f, 0.0f};   // ones-column accum (row sums)

    const uint32_t aQrow = sb + SMQ_OFF + (m0w + (lane & 15)) * 144 + ((lane >> 4) << 4);
    const uint32_t bRowSel = (((lane >> 4) & 1) << 3) + (lane & 7);
    const uint32_t bKhi    = ((lane >> 3) & 1) << 4;
    const int sh = 2 * tig;

    const uint32_t* mb0 = g_mask_bits + ((size_t)(n * Ll + q0 + m0w + gid)) * (Ll / 32);
    const uint32_t* mb1 = mb0 + (size_t)8 * (Ll / 32);

    for (int kt = 0; kt < NT; kt++) {
        if (kt + 1 < NT) {
            const __half* kb = g_kh + ((size_t)(n * Ll + (kt + 1) * 64)) * Ee + h * Dd;
            const __half* vb = g_vt + ((size_t)(n * Hh + h) * Dd) * Ll + (kt + 1) * 64;
            uint32_t st = sb + SMK_OFF + ((kt + 1) & 1) * STAGE;
            #pragma unroll
            for (int i = 0; i < 2; i++) {
                int idx = tid + i * 256;
                int r = idx >> 3, c = idx & 7;
                CPA16(st + r * 144 + c * 16, kb + (size_t)r * Ee + c * 8);
                CPA16(st + VOFF + r * 144 + c * 16, vb + (size_t)r * Ll + c * 8);
            }
        }
        CPA_COMMIT();
        CPA_WAIT1();
        __syncthreads();

        const uint32_t kbase = sb + SMK_OFF + (kt & 1) * STAGE;
        const uint32_t vbase = kbase + VOFF;

        // pre-shift mask words so tile t's pair sits at bits (t&3)*8, +1
        uint32_t w0a = mb0[kt * 2] >> sh, w0b = mb0[kt * 2 + 1] >> sh;
        uint32_t w1a = mb1[kt * 2] >> sh, w1b = mb1[kt * 2 + 1] >> sh;

        // ---- S = Q K^T : warp m16 x n64 ----
        float S[8][4];
        #pragma unroll
        for (int t = 0; t < 8; t++)
            #pragma unroll
            for (int j = 0; j < 4; j++) S[t][j] = 0.0f;

        #pragma unroll
        for (int kc = 0; kc < 4; kc++) {
            uint32_t a0, a1, a2, a3;
            ldmx4(a0, a1, a2, a3, aQrow + kc * 32);
            #pragma unroll
            for (int j = 0; j < 4; j++) {
                uint32_t b0, b1, b2, b3;
                ldmx4(b0, b1, b2, b3,
                      kbase + (j * 16 + bRowSel) * 144 + kc * 32 + bKhi);
                mma16816(S[2 * j],     a0, a1, a2, a3, b0, b1);
                mma16816(S[2 * j + 1], a0, a1, a2, a3, b2, b3);
            }
        }

        // ---- P = exp2(S) packed fp16x2, masked by ISETP/SEL half-masks ----
        uint32_t Ap0[8], Ap1[8];
        #pragma unroll
        for (int t = 0; t < 8; t++) {
            const int k4 = t & 3;
            uint32_t ba = (((t < 4) ? w0a : w0b) >> (k4 * 8)) & 3u;
            uint32_t bb = (((t < 4) ? w1a : w1b) >> (k4 * 8)) & 3u;
            uint32_t e01 = ex2_h2(cvt_h2(S[t][0], S[t][1]));
            uint32_t e23 = ex2_h2(cvt_h2(S[t][2], S[t][3]));
            uint32_t m0 = ((ba & 1u) ? 0x0000FFFFu : 0u) | ((ba & 2u) ? 0xFFFF0000u : 0u);
            uint32_t m1 = ((bb & 1u) ? 0x0000FFFFu : 0u) | ((bb & 2u) ? 0xFFFF0000u : 0u);
            Ap0[t] = e01 & m0;
            Ap1[t] = e23 & m1;
        }

        // ---- O += P V ; row sums via ones-rows (V rows 64..79, row64 = 1) ----
        #pragma unroll
        for (int kc = 0; kc < 4; kc++) {
            uint32_t a0 = Ap0[2 * kc], a1 = Ap1[2 * kc];
            uint32_t a2 = Ap0[2 * kc + 1], a3 = Ap1[2 * kc + 1];
            #pragma unroll
            for (int j = 0; j < 4; j++) {
                uint32_t b0, b1, b2, b3;
                ldmx4(b0, b1, b2, b3,
                      vbase + (j * 16 + bRowSel) * 144 + kc * 32 + bKhi);
                mma16816(O[2 * j],     a0, a1, a2, a3, b0, b1);
                mma16816(O[2 * j + 1], a0, a1, a2, a3, b2, b3);
            }
            uint32_t c0, c1, c2, c3;
            ldmx4(c0, c1, c2, c3,
                  vbase + (64 + bRowSel) * 144 + kc * 32 + bKhi);
            mma16816(Cl, a0, a1, a2, a3, c0, c1);
        }
        __syncthreads();
    }

    // ---- lsum = Cl col 0 -> tig==0 lanes' c0/c2; broadcast within quad ----
    float lsum0 = __shfl_sync(0xffffffffu, Cl[0], (lane >> 2) << 2);
    float lsum1 = __shfl_sync(0xffffffffu, Cl[2], (lane >> 2) << 2);
    float inv0 = 1.0f / lsum0, inv1 = 1.0f / lsum1;

    __half* ob0 = g_attn_half + ((size_t)(n * Ll + q0 + m0w + gid)) * Ee + h * Dd;
    __half* ob1 = ob0 + (size_t)8 * Ee;
    #pragma unroll
    for (int t = 0; t < 8; t++) {
        *reinterpret_cast<uint32_t*>(ob0 + t * 8 + 2 * tig) =
            h2u(__floats2half2_rn(O[t][0] * inv0, O[t][1] * inv0));
        *reinterpret_cast<uint32_t*>(ob1 + t * 8 + 2 * tig) =
            h2u(__floats2half2_rn(O[t][2] * inv1, O[t][3] * inv1));
    }
}

// ===========================================================================
// Projection: out = X W^T + b. fp16 mma, 128x128 tiles, double-buffered.
// ===========================================================================
#define PJ_STAGE (2 * 128 * SQH * 2)
#define PJ_TOTAL (2 * PJ_STAGE)

__global__ __launch_bounds__(256) void proj_hmma(
    const float* __restrict__ bias, float* __restrict__ out)
{
    extern __shared__ __align__(16) char smem[];
    const uint32_t sb = smem_u32(smem);
    const int tid = threadIdx.x;
    const int lane = tid & 31;
    const int wid = tid >> 5;
    const int gid = lane >> 2, tig = lane & 3;
    const int n0 = blockIdx.x * 128;
    const int m0 = blockIdx.y * 128;
    const int m0w = wid * 16;

    const uint32_t bRowSel = (((lane >> 4) & 1) << 3) + (lane & 7);
    const uint32_t bKhi    = ((lane >> 3) & 1) << 4;

    auto issue = [&](int kc) {
        const __half* xb = g_attn_half + (size_t)m0 * Ee + kc * 64;
        const __half* wb = g_wh + (size_t)n0 * Ee + kc * 64;
        uint32_t st = sb + (kc & 1) * PJ_STAGE;
        #pragma unroll
        for (int i = 0; i < 4; i++) {
            int idx = tid + i * 256;
            int r = idx >> 3, c = idx & 7;
            CPA16(st + r * 144 + c * 16, xb + (size_t)r * Ee + c * 8);
            CPA16(st + 128 * SQH * 2 + r * 144 + c * 16, wb + (size_t)r * Ee + c * 8);
        }
    };

    float C[16][4];
    #pragma unroll
    for (int t = 0; t < 16; t++)
        #pragma unroll
        for (int j = 0; j < 4; j++) C[t][j] = 0.0f;

    issue(0);
    CPA_COMMIT();

    for (int kc = 0; kc < Ee / 64; kc++) {
        if (kc + 1 < Ee / 64) issue(kc + 1);
        CPA_COMMIT();
        CPA_WAIT1();
        __syncthreads();

        const uint32_t xbase = sb + (kc & 1) * PJ_STAGE;
        const uint32_t wbase = xbase + 128 * SQH * 2;
        const uint32_t aXrow = xbase + (m0w + (lane & 15)) * 144 + ((lane >> 4) << 4);

        #pragma unroll
        for (int k4 = 0; k4 < 4; k4++) {
            uint32_t a0, a1, a2, a3;
            ldmx4(a0, a1, a2, a3, aXrow + k4 * 32);
            #pragma unroll
            for (int j = 0; j < 8; j++) {
                uint32_t b0, b1, b2, b3;
                ldmx4(b0, b1, b2, b3,
                      wbase + (j * 16 + bRowSel) * 144 + k4 * 32 + bKhi);
                mma16816(C[2 * j],     a0, a1, a2, a3, b0, b1);
                mma16816(C[2 * j + 1], a0, a1, a2, a3, b2, b3);
            }
        }
        __syncthreads();
    }

    float* ob0 = out + (size_t)(m0 + m0w + gid) * Ee + n0;
    float* ob1 = ob0 + (size_t)8 * Ee;
    #pragma unroll
    for (int t = 0; t < 16; t++) {
        float2 bv = *reinterpret_cast<const float2*>(bias + n0 + t * 8 + 2 * tig);
        *reinterpret_cast<float2*>(ob0 + t * 8 + 2 * tig) =
            make_float2(C[t][0] + bv.x, C[t][1] + bv.y);
        *reinterpret_cast<float2*>(ob1 + t * 8 + 2 * tig) =
            make_float2(C[t][2] + bv.x, C[t][3] + bv.y);
    }
}

// ===========================================================================
extern "C" void kernel_launch(void* const* d_in, const int* in_sizes, int n_in,
                              void* d_out, int out_size)
{
    const float* Q = (const float*)d_in[0];
    const float* K = (const float*)d_in[1];
    const float* V = (const float*)d_in[2];
    const int*   M = (const int*)d_in[3];
    const float* W = (const float*)d_in[4];
    const float* b = (const float*)d_in[5];
    float* out = (float*)d_out;

    conv_qkw<<<2048, 256>>>(Q, K, W);
    {
        dim3 g(Ll / 64, Nn * Hh);
        v_transpose<<<g, 256>>>(V);
    }
    {
        size_t nwords = (size_t)Nn * Ll * (Ll / 32);
        size_t nwarps = (nwords + 7) / 8;
        mask_pack<<<(int)((nwarps + 7) / 8), 256>>>(M);
    }

    cudaFuncSetAttribute(attn_hmma,
                         cudaFuncAttributeMaxDynamicSharedMemorySize, SM_ATT_TOTAL);
    {
        dim3 g(Ll / 128, Nn * Hh);
        attn_hmma<<<g, 256, SM_ATT_TOTAL>>>(M);
    }

    cudaFuncSetAttribute(proj_hmma,
                         cudaFuncAttributeMaxDynamicSharedMemorySize, PJ_TOTAL);
    {
        dim3 g(Ee / 128, (Nn * Ll) / 128);
        proj_hmma<<<g, 256, PJ_TOTAL>>>(b, out);
    }
}

// round 7
// speedup vs baseline: 8.0136x; 1.0052x over previous
#include <cuda_runtime.h>
#include <cuda_fp16.h>
#include <cstdint>

// Problem constants
#define Nn 2
#define Ll 2048
#define Ee 1024
#define Hh 16
#define Dd 64
#define NT (Ll / 64)      // 32 key tiles
#define SQH 72            // smem row stride in halves (144 B)

// Static device scratch (allocation-free per harness rules)
__device__ __align__(16) __half   g_qh[(size_t)Nn * Ll * Ee];        // Q * log2e/32
__device__ __align__(16) __half   g_kh[(size_t)Nn * Ll * Ee];        // K fp16
__device__ __align__(16) __half   g_vt[(size_t)Nn * Hh * Dd * Ll];   // V fp16 transposed
__device__ __align__(16) __half   g_attn_half[(size_t)Nn * Ll * Ee]; // attention out fp16
__device__ __align__(16) __half   g_wh[(size_t)Ee * Ee];             // W fp16
__device__ __align__(16) uint32_t g_mask_bits[(size_t)Nn * Ll * (Ll / 32)];

// ---------------------------------------------------------------------------
// helpers
// ---------------------------------------------------------------------------
__device__ __forceinline__ uint32_t smem_u32(const void* p) {
    uint32_t a;
    asm("{ .reg .u64 t; cvta.to.shared.u64 t, %1; cvt.u32.u64 %0, t; }"
        : "=r"(a) : "l"(p));
    return a;
}

__device__ __forceinline__ void ldmx4(uint32_t& r0, uint32_t& r1,
                                      uint32_t& r2, uint32_t& r3, uint32_t addr) {
    asm volatile("ldmatrix.sync.aligned.m8n8.x4.shared.b16 {%0,%1,%2,%3}, [%4];"
                 : "=r"(r0), "=r"(r1), "=r"(r2), "=r"(r3) : "r"(addr));
}

__device__ __forceinline__ void mma16816(float c[4], uint32_t a0, uint32_t a1,
                                         uint32_t a2, uint32_t a3,
                                         uint32_t b0, uint32_t b1) {
    asm volatile(
        "mma.sync.aligned.m16n8k16.row.col.f32.f16.f16.f32 "
        "{%0,%1,%2,%3},{%4,%5,%6,%7},{%8,%9},{%0,%1,%2,%3};"
        : "+f"(c[0]), "+f"(c[1]), "+f"(c[2]), "+f"(c[3])
        : "r"(a0), "r"(a1), "r"(a2), "r"(a3), "r"(b0), "r"(b1));
}

// pack 2 floats to half2 bits: lo -> low half, hi -> high half
__device__ __forceinline__ uint32_t cvt_h2(float lo, float hi) {
    uint32_t d;
    asm("cvt.rn.f16x2.f32 %0, %1, %2;" : "=r"(d) : "f"(hi), "f"(lo));
    return d;
}
// 2^x on both halves
__device__ __forceinline__ uint32_t ex2_h2(uint32_t s) {
    uint32_t d;
    asm("ex2.approx.f16x2 %0, %1;" : "=r"(d) : "r"(s));
    return d;
}
// fp16x2 add (FMA-pipe, rt 2)
__device__ __forceinline__ uint32_t hadd2u(uint32_t a, uint32_t b) {
    uint32_t d;
    asm("add.f16x2 %0, %1, %2;" : "=r"(d) : "r"(a), "r"(b));
    return d;
}

#define CPA16(dst, src) \
    asm volatile("cp.async.cg.shared.global [%0], [%1], 16;" :: "r"(dst), "l"(src))
#define CPA_COMMIT() asm volatile("cp.async.commit_group;" ::: "memory")
#define CPA_WAIT1()  asm volatile("cp.async.wait_group 1;" ::: "memory")

__device__ __forceinline__ uint32_t h2u(__half2 h) { return *reinterpret_cast<uint32_t*>(&h); }

// ===========================================================================
// Prepass 1: convert Q (scaled log2e/32), K, W to fp16
// ===========================================================================
#define EQ ((size_t)Nn * Ll * Ee)
#define EW ((size_t)Ee * Ee)
__global__ __launch_bounds__(256) void conv_qkw(
    const float* __restrict__ Q, const float* __restrict__ K,
    const float* __restrict__ W)
{
    const size_t q4 = EQ / 4, k4 = EQ / 4, w4 = EW / 4;
    const size_t tot = q4 + k4 + w4;
    const float QSC = 0.045084437f;   // log2(e)/32
    for (size_t i = (size_t)blockIdx.x * 256 + threadIdx.x; i < tot;
         i += (size_t)gridDim.x * 256) {
        const float* src; __half* dst; float sc; size_t j;
        if (i < q4)            { src = Q; dst = g_qh; sc = QSC; j = i; }
        else if (i < q4 + k4)  { src = K; dst = g_kh; sc = 1.0f; j = i - q4; }
        else                   { src = W; dst = g_wh; sc = 1.0f; j = i - q4 - k4; }
        float4 v = reinterpret_cast<const float4*>(src)[j];
        __half2 h0 = __floats2half2_rn(v.x * sc, v.y * sc);
        __half2 h1 = __floats2half2_rn(v.z * sc, v.w * sc);
        reinterpret_cast<uint2*>(dst)[j] = make_uint2(h2u(h0), h2u(h1));
    }
}

// ===========================================================================
// Prepass 2: V -> fp16 transposed g_vt[n][h][d][l]
// ===========================================================================
__global__ __launch_bounds__(256) void v_transpose(const float* __restrict__ V) {
    __shared__ float sm[64][65];
    const int l0 = blockIdx.x * 64;
    const int n  = blockIdx.y >> 4;
    const int h  = blockIdx.y & 15;
    const int tid = threadIdx.x;
    const float* vb = V + ((size_t)(n * Ll + l0)) * Ee + h * Dd;
    for (int idx = tid; idx < 64 * 16; idx += 256) {
        int r = idx >> 4, c4 = idx & 15;
        float4 v = *reinterpret_cast<const float4*>(vb + (size_t)r * Ee + c4 * 4);
        sm[r][c4 * 4 + 0] = v.x; sm[r][c4 * 4 + 1] = v.y;
        sm[r][c4 * 4 + 2] = v.z; sm[r][c4 * 4 + 3] = v.w;
    }
    __syncthreads();
    const int d = tid >> 2;
    const int lb = (tid & 3) * 16;
    __half* ob = g_vt + (((size_t)(n * Hh + h) * Dd + d)) * Ll + l0 + lb;
    uint32_t pk[8];
    #pragma unroll
    for (int i = 0; i < 8; i++)
        pk[i] = h2u(__floats2half2_rn(sm[lb + 2 * i][d], sm[lb + 2 * i + 1][d]));
    *reinterpret_cast<uint4*>(ob)     = make_uint4(pk[0], pk[1], pk[2], pk[3]);
    *reinterpret_cast<uint4*>(ob + 8) = make_uint4(pk[4], pk[5], pk[6], pk[7]);
}

// ===========================================================================
// Prepass 3: mask -> bitmask, 8 words per warp
// ===========================================================================
__global__ __launch_bounds__(256) void mask_pack(const int* __restrict__ M) {
    const size_t nwords = (size_t)Nn * Ll * (Ll / 32);
    size_t wbase = (((size_t)blockIdx.x * 256 + threadIdx.x) >> 5) * 8;
    int lane = threadIdx.x & 31;
    if (wbase >= nwords) return;
    int v[8];
    #pragma unroll
    for (int j = 0; j < 8; j++) v[j] = M[(wbase + j) * 32 + lane];
    uint32_t b[8];
    #pragma unroll
    for (int j = 0; j < 8; j++) b[j] = __ballot_sync(0xffffffffu, v[j] != 0);
    if (lane == 0) {
        *reinterpret_cast<uint4*>(&g_mask_bits[wbase])     = make_uint4(b[0], b[1], b[2], b[3]);
        *reinterpret_cast<uint4*>(&g_mask_bits[wbase + 4]) = make_uint4(b[4], b[5], b[6], b[7]);
    }
}

// ===========================================================================
// Flash attention. fp16 mma + ldmatrix; Q fragments hoisted to registers;
// softmax via packed fp16x2 ex2 + ISETP/SEL masks; lsum via HADD2 tree.
// Grid (L/128, N*H) = (16, 32), 256 threads = 8 warps (16 q-rows each).
// ===========================================================================
#define SMQ_OFF 0
#define SMK_OFF (128 * SQH * 2)              // 18432
#define VOFF    (64 * SQH * 2)               // 9216 (V within stage)
#define STAGE   (2 * 64 * SQH * 2)           // K 64 + V 64 rows = 18432
#define SM_ATT_TOTAL (SMK_OFF + 2 * STAGE)   // 55296 B

__global__ __launch_bounds__(256) void attn_hmma(
    const int* __restrict__ dummy)
{
    extern __shared__ __align__(16) char smem[];
    const uint32_t sb = smem_u32(smem);
    const int tid = threadIdx.x;
    const int lane = tid & 31;
    const int wid = tid >> 5;
    const int gid = lane >> 2, tig = lane & 3;
    const int n = blockIdx.y >> 4;
    const int h = blockIdx.y & 15;
    const int q0 = blockIdx.x * 128;
    const int m0w = wid * 16;

    // ---- preload Q (128 rows) + tile 0 (K/V) via cp.async ----
    {
        const __half* qb = g_qh + ((size_t)(n * Ll + q0)) * Ee + h * Dd;
        #pragma unroll
        for (int i = 0; i < 4; i++) {
            int idx = tid + i * 256;
            int r = idx >> 3, c = idx & 7;
            CPA16(sb + SMQ_OFF + r * 144 + c * 16, qb + (size_t)r * Ee + c * 8);
        }
        const __half* kb = g_kh + ((size_t)(n * Ll)) * Ee + h * Dd;
        const __half* vb = g_vt + ((size_t)(n * Hh + h) * Dd) * Ll;
        #pragma unroll
        for (int i = 0; i < 2; i++) {
            int idx = tid + i * 256;
            int r = idx >> 3, c = idx & 7;
            CPA16(sb + SMK_OFF + r * 144 + c * 16, kb + (size_t)r * Ee + c * 8);
            CPA16(sb + SMK_OFF + VOFF + r * 144 + c * 16, vb + (size_t)r * Ll + c * 8);
        }
        CPA_COMMIT();
    }

    float O[8][4];
    #pragma unroll
    for (int t = 0; t < 8; t++)
        #pragma unroll
        for (int j = 0; j < 4; j++) O[t][j] = 0.0f;
    float lsum0 = 0.0f, lsum1 = 0.0f;
    uint32_t qf[4][4];                       // Q fragments, loaded once

    const uint32_t aQrow = sb + SMQ_OFF + (m0w + (lane & 15)) * 144 + ((lane >> 4) << 4);
    const uint32_t bRowSel = (((lane >> 4) & 1) << 3) + (lane & 7);
    const uint32_t bKhi    = ((lane >> 3) & 1) << 4;
    const int sh = 2 * tig;

    const uint32_t* mb0 = g_mask_bits + ((size_t)(n * Ll + q0 + m0w + gid)) * (Ll / 32);
    const uint32_t* mb1 = mb0 + (size_t)8 * (Ll / 32);

    for (int kt = 0; kt < NT; kt++) {
        if (kt + 1 < NT) {
            const __half* kb = g_kh + ((size_t)(n * Ll + (kt + 1) * 64)) * Ee + h * Dd;
            const __half* vb = g_vt + ((size_t)(n * Hh + h) * Dd) * Ll + (kt + 1) * 64;
            uint32_t st = sb + SMK_OFF + ((kt + 1) & 1) * STAGE;
            #pragma unroll
            for (int i = 0; i < 2; i++) {
                int idx = tid + i * 256;
                int r = idx >> 3, c = idx & 7;
                CPA16(st + r * 144 + c * 16, kb + (size_t)r * Ee + c * 8);
                CPA16(st + VOFF + r * 144 + c * 16, vb + (size_t)r * Ll + c * 8);
            }
        }
        CPA_COMMIT();
        CPA_WAIT1();
        __syncthreads();

        if (kt == 0) {   // Q now resident: hoist fragments into registers
            #pragma unroll
            for (int kc = 0; kc < 4; kc++)
                ldmx4(qf[kc][0], qf[kc][1], qf[kc][2], qf[kc][3], aQrow + kc * 32);
        }

        const uint32_t kbase = sb + SMK_OFF + (kt & 1) * STAGE;
        const uint32_t vbase = kbase + VOFF;

        uint32_t w0a = mb0[kt * 2] >> sh, w0b = mb0[kt * 2 + 1] >> sh;
        uint32_t w1a = mb1[kt * 2] >> sh, w1b = mb1[kt * 2 + 1] >> sh;

        // ---- S = Q K^T : warp m16 x n64 ----
        float S[8][4];
        #pragma unroll
        for (int t = 0; t < 8; t++)
            #pragma unroll
            for (int j = 0; j < 4; j++) S[t][j] = 0.0f;

        #pragma unroll
        for (int kc = 0; kc < 4; kc++) {
            #pragma unroll
            for (int j = 0; j < 4; j++) {
                uint32_t b0, b1, b2, b3;
                ldmx4(b0, b1, b2, b3,
                      kbase + (j * 16 + bRowSel) * 144 + kc * 32 + bKhi);
                mma16816(S[2 * j],     qf[kc][0], qf[kc][1], qf[kc][2], qf[kc][3], b0, b1);
                mma16816(S[2 * j + 1], qf[kc][0], qf[kc][1], qf[kc][2], qf[kc][3], b2, b3);
            }
        }

        // ---- P = exp2(S) packed fp16x2, masked ----
        uint32_t Ap0[8], Ap1[8];
        #pragma unroll
        for (int t = 0; t < 8; t++) {
            const int k4 = t & 3;
            uint32_t ba = (((t < 4) ? w0a : w0b) >> (k4 * 8)) & 3u;
            uint32_t bb = (((t < 4) ? w1a : w1b) >> (k4 * 8)) & 3u;
            uint32_t e01 = ex2_h2(cvt_h2(S[t][0], S[t][1]));
            uint32_t e23 = ex2_h2(cvt_h2(S[t][2], S[t][3]));
            uint32_t m0 = ((ba & 1u) ? 0x0000FFFFu : 0u) | ((ba & 2u) ? 0xFFFF0000u : 0u);
            uint32_t m1 = ((bb & 1u) ? 0x0000FFFFu : 0u) | ((bb & 2u) ? 0xFFFF0000u : 0u);
            Ap0[t] = e01 & m0;
            Ap1[t] = e23 & m1;
        }

        // ---- per-tile row-sum: HADD2 tree (fma pipe) + fp32 accumulate ----
        {
            uint32_t s0 = hadd2u(hadd2u(hadd2u(Ap0[0], Ap0[1]), hadd2u(Ap0[2], Ap0[3])),
                                 hadd2u(hadd2u(Ap0[4], Ap0[5]), hadd2u(Ap0[6], Ap0[7])));
            uint32_t s1 = hadd2u(hadd2u(hadd2u(Ap1[0], Ap1[1]), hadd2u(Ap1[2], Ap1[3])),
                                 hadd2u(hadd2u(Ap1[4], Ap1[5]), hadd2u(Ap1[6], Ap1[7])));
            float2 f0 = __half22float2(*reinterpret_cast<__half2*>(&s0));
            float2 f1 = __half22float2(*reinterpret_cast<__half2*>(&s1));
            lsum0 += f0.x + f0.y;
            lsum1 += f1.x + f1.y;
        }

        // ---- O += P V ----
        #pragma unroll
        for (int kc = 0; kc < 4; kc++) {
            uint32_t a0 = Ap0[2 * kc], a1 = Ap1[2 * kc];
            uint32_t a2 = Ap0[2 * kc + 1], a3 = Ap1[2 * kc + 1];
            #pragma unroll
            for (int j = 0; j < 4; j++) {
                uint32_t b0, b1, b2, b3;
                ldmx4(b0, b1, b2, b3,
                      vbase + (j * 16 + bRowSel) * 144 + kc * 32 + bKhi);
                mma16816(O[2 * j],     a0, a1, a2, a3, b0, b1);
                mma16816(O[2 * j + 1], a0, a1, a2, a3, b2, b3);
            }
        }
        __syncthreads();
    }

    // ---- reduce row sums over the 4 tig lanes, normalize, store fp16 ----
    lsum0 += __shfl_xor_sync(0xffffffffu, lsum0, 1);
    lsum0 += __shfl_xor_sync(0xffffffffu, lsum0, 2);
    lsum1 += __shfl_xor_sync(0xffffffffu, lsum1, 1);
    lsum1 += __shfl_xor_sync(0xffffffffu, lsum1, 2);
    float inv0 = 1.0f / lsum0, inv1 = 1.0f / lsum1;

    __half* ob0 = g_attn_half + ((size_t)(n * Ll + q0 + m0w + gid)) * Ee + h * Dd;
    __half* ob1 = ob0 + (size_t)8 * Ee;
    #pragma unroll
    for (int t = 0; t < 8; t++) {
        *reinterpret_cast<uint32_t*>(ob0 + t * 8 + 2 * tig) =
            h2u(__floats2half2_rn(O[t][0] * inv0, O[t][1] * inv0));
        *reinterpret_cast<uint32_t*>(ob1 + t * 8 + 2 * tig) =
            h2u(__floats2half2_rn(O[t][2] * inv1, O[t][3] * inv1));
    }
}

// ===========================================================================
// Projection: out = X W^T + b. fp16 mma, CTA 128x128, warp tile m32 x n64
// (4 m-warps x 2 n-warps) -> W-fragment traffic per warp drops 33%.
// ===========================================================================
#define PJ_STAGE (2 * 128 * SQH * 2)
#define PJ_TOTAL (2 * PJ_STAGE)

__global__ __launch_bounds__(256) void proj_hmma(
    const float* __restrict__ bias, float* __restrict__ out)
{
    extern __shared__ __align__(16) char smem[];
    const uint32_t sb = smem_u32(smem);
    const int tid = threadIdx.x;
    const int lane = tid & 31;
    const int wid = tid >> 5;
    const int gid = lane >> 2, tig = lane & 3;
    const int n0 = blockIdx.x * 128;
    const int m0 = blockIdx.y * 128;
    const int mw = wid & 3, nw = wid >> 2;
    const int m0w = mw * 32;
    const int n0w = nw * 64;

    const uint32_t bRowSel = (((lane >> 4) & 1) << 3) + (lane & 7);
    const uint32_t bKhi    = ((lane >> 3) & 1) << 4;

    auto issue = [&](int kc) {
        const __half* xb = g_attn_half + (size_t)m0 * Ee + kc * 64;
        const __half* wb = g_wh + (size_t)n0 * Ee + kc * 64;
        uint32_t st = sb + (kc & 1) * PJ_STAGE;
        #pragma unroll
        for (int i = 0; i < 4; i++) {
            int idx = tid + i * 256;
            int r = idx >> 3, c = idx & 7;
            CPA16(st + r * 144 + c * 16, xb + (size_t)r * Ee + c * 8);
            CPA16(st + 128 * SQH * 2 + r * 144 + c * 16, wb + (size_t)r * Ee + c * 8);
        }
    };

    float C[2][8][4];   // [m-half][n8-tile][frag]
    #pragma unroll
    for (int hh = 0; hh < 2; hh++)
        #pragma unroll
        for (int t = 0; t < 8; t++)
            #pragma unroll
            for (int j = 0; j < 4; j++) C[hh][t][j] = 0.0f;

    issue(0);
    CPA_COMMIT();

    for (int kc = 0; kc < Ee / 64; kc++) {
        if (kc + 1 < Ee / 64) issue(kc + 1);
        CPA_COMMIT();
        CPA_WAIT1();
        __syncthreads();

        const uint32_t xbase = sb + (kc & 1) * PJ_STAGE;
        const uint32_t wbase = xbase + 128 * SQH * 2;

        #pragma unroll
        for (int k4 = 0; k4 < 4; k4++) {
            uint32_t a[2][4];
            #pragma unroll
            for (int hh = 0; hh < 2; hh++)
                ldmx4(a[hh][0], a[hh][1], a[hh][2], a[hh][3],
                      xbase + (m0w + hh * 16 + (lane & 15)) * 144 +
                      ((lane >> 4) << 4) + k4 * 32);
            #pragma unroll
            for (int j = 0; j < 4; j++) {
                uint32_t b0, b1, b2, b3;
                ldmx4(b0, b1, b2, b3,
                      wbase + (n0w + j * 16 + bRowSel) * 144 + k4 * 32 + bKhi);
                #pragma unroll
                for (int hh = 0; hh < 2; hh++) {
                    mma16816(C[hh][2 * j],     a[hh][0], a[hh][1], a[hh][2], a[hh][3], b0, b1);
                    mma16816(C[hh][2 * j + 1], a[hh][0], a[hh][1], a[hh][2], a[hh][3], b2, b3);
                }
            }
        }
        __syncthreads();
    }

    #pragma unroll
    for (int hh = 0; hh < 2; hh++) {
        float* ob0 = out + (size_t)(m0 + m0w + hh * 16 + gid) * Ee + n0 + n0w;
        float* ob1 = ob0 + (size_t)8 * Ee;
        #pragma unroll
        for (int t = 0; t < 8; t++) {
            float2 bv = *reinterpret_cast<const float2*>(bias + n0 + n0w + t * 8 + 2 * tig);
            *reinterpret_cast<float2*>(ob0 + t * 8 + 2 * tig) =
                make_float2(C[hh][t][0] + bv.x, C[hh][t][1] + bv.y);
            *reinterpret_cast<float2*>(ob1 + t * 8 + 2 * tig) =
                make_float2(C[hh][t][2] + bv.x, C[hh][t][3] + bv.y);
        }
    }
}

// ===========================================================================
extern "C" void kernel_launch(void* const* d_in, const int* in_sizes, int n_in,
                              void* d_out, int out_size)
{
    const float* Q = (const float*)d_in[0];
    const float* K = (const float*)d_in[1];
    const float* V = (const float*)d_in[2];
    const int*   M = (const int*)d_in[3];
    const float* W = (const float*)d_in[4];
    const float* b = (const float*)d_in[5];
    float* out = (float*)d_out;

    conv_qkw<<<2048, 256>>>(Q, K, W);
    {
        dim3 g(Ll / 64, Nn * Hh);
        v_transpose<<<g, 256>>>(V);
    }
    {
        size_t nwords = (size_t)Nn * Ll * (Ll / 32);
        size_t nwarps = (nwords + 7) / 8;
        mask_pack<<<(int)((nwarps + 7) / 8), 256>>>(M);
    }

    cudaFuncSetAttribute(attn_hmma,
                         cudaFuncAttributeMaxDynamicSharedMemorySize, SM_ATT_TOTAL);
    {
        dim3 g(Ll / 128, Nn * Hh);
        attn_hmma<<<g, 256, SM_ATT_TOTAL>>>(M);
    }

    cudaFuncSetAttribute(proj_hmma,
                         cudaFuncAttributeMaxDynamicSharedMemorySize, PJ_TOTAL);
    {
        dim3 g(Ee / 128, (Nn * Ll) / 128);
        proj_hmma<<<g, 256, PJ_TOTAL>>>(b, out);
    }
}

// round 8
// speedup vs baseline: 8.1495x; 1.0170x over previous
#include <cuda_runtime.h>
#include <cuda_fp16.h>
#include <cstdint>

// Problem constants
#define Nn 2
#define Ll 2048
#define Ee 1024
#define Hh 16
#define Dd 64
#define NT (Ll / 64)      // 32 key tiles
#define SQH 72            // smem row stride in halves (144 B)

// Static device scratch (allocation-free per harness rules)
__device__ __align__(16) __half   g_qh[(size_t)Nn * Ll * Ee];        // Q * log2e/32
__device__ __align__(16) __half   g_kh[(size_t)Nn * Ll * Ee];        // K fp16
__device__ __align__(16) __half   g_vt[(size_t)Nn * Hh * Dd * Ll];   // V fp16 transposed
__device__ __align__(16) __half   g_attn_half[(size_t)Nn * Ll * Ee]; // attention out fp16
__device__ __align__(16) __half   g_wh[(size_t)Ee * Ee];             // W fp16
__device__ __align__(16) uint32_t g_mask_bits[(size_t)Nn * Ll * (Ll / 32)];

// ---------------------------------------------------------------------------
// helpers
// ---------------------------------------------------------------------------
__device__ __forceinline__ uint32_t smem_u32(const void* p) {
    uint32_t a;
    asm("{ .reg .u64 t; cvta.to.shared.u64 t, %1; cvt.u32.u64 %0, t; }"
        : "=r"(a) : "l"(p));
    return a;
}

__device__ __forceinline__ void ldmx4(uint32_t& r0, uint32_t& r1,
                                      uint32_t& r2, uint32_t& r3, uint32_t addr) {
    asm volatile("ldmatrix.sync.aligned.m8n8.x4.shared.b16 {%0,%1,%2,%3}, [%4];"
                 : "=r"(r0), "=r"(r1), "=r"(r2), "=r"(r3) : "r"(addr));
}

__device__ __forceinline__ void mma16816(float c[4], uint32_t a0, uint32_t a1,
                                         uint32_t a2, uint32_t a3,
                                         uint32_t b0, uint32_t b1) {
    asm volatile(
        "mma.sync.aligned.m16n8k16.row.col.f32.f16.f16.f32 "
        "{%0,%1,%2,%3},{%4,%5,%6,%7},{%8,%9},{%0,%1,%2,%3};"
        : "+f"(c[0]), "+f"(c[1]), "+f"(c[2]), "+f"(c[3])
        : "r"(a0), "r"(a1), "r"(a2), "r"(a3), "r"(b0), "r"(b1));
}

// pack 2 floats to half2 bits: lo -> low half, hi -> high half
__device__ __forceinline__ uint32_t cvt_h2(float lo, float hi) {
    uint32_t d;
    asm("cvt.rn.f16x2.f32 %0, %1, %2;" : "=r"(d) : "f"(hi), "f"(lo));
    return d;
}
// 2^x on both halves
__device__ __forceinline__ uint32_t ex2_h2(uint32_t s) {
    uint32_t d;
    asm("ex2.approx.f16x2 %0, %1;" : "=r"(d) : "r"(s));
    return d;
}
// fp16x2 add (FMA-pipe)
__device__ __forceinline__ uint32_t hadd2u(uint32_t a, uint32_t b) {
    uint32_t d;
    asm("add.f16x2 %0, %1, %2;" : "=r"(d) : "r"(a), "r"(b));
    return d;
}

#define CPA16(dst, src) \
    asm volatile("cp.async.cg.shared.global [%0], [%1], 16;" :: "r"(dst), "l"(src))
#define CPA_COMMIT() asm volatile("cp.async.commit_group;" ::: "memory")
#define CPA_WAIT1()  asm volatile("cp.async.wait_group 1;" ::: "memory")

__device__ __forceinline__ uint32_t h2u(__half2 h) { return *reinterpret_cast<uint32_t*>(&h); }

// ===========================================================================
// Prepass 1: convert Q (scaled log2e/32), K, W to fp16
// ===========================================================================
#define EQ ((size_t)Nn * Ll * Ee)
#define EW ((size_t)Ee * Ee)
__global__ __launch_bounds__(256) void conv_qkw(
    const float* __restrict__ Q, const float* __restrict__ K,
    const float* __restrict__ W)
{
    const size_t q4 = EQ / 4, k4 = EQ / 4, w4 = EW / 4;
    const size_t tot = q4 + k4 + w4;
    const float QSC = 0.045084437f;   // log2(e)/32
    for (size_t i = (size_t)blockIdx.x * 256 + threadIdx.x; i < tot;
         i += (size_t)gridDim.x * 256) {
        const float* src; __half* dst; float sc; size_t j;
        if (i < q4)            { src = Q; dst = g_qh; sc = QSC; j = i; }
        else if (i < q4 + k4)  { src = K; dst = g_kh; sc = 1.0f; j = i - q4; }
        else                   { src = W; dst = g_wh; sc = 1.0f; j = i - q4 - k4; }
        float4 v = reinterpret_cast<const float4*>(src)[j];
        __half2 h0 = __floats2half2_rn(v.x * sc, v.y * sc);
        __half2 h1 = __floats2half2_rn(v.z * sc, v.w * sc);
        reinterpret_cast<uint2*>(dst)[j] = make_uint2(h2u(h0), h2u(h1));
    }
}

// ===========================================================================
// Prepass 2: V -> fp16 transposed g_vt[n][h][d][l]
// ===========================================================================
__global__ __launch_bounds__(256) void v_transpose(const float* __restrict__ V) {
    __shared__ float sm[64][65];
    const int l0 = blockIdx.x * 64;
    const int n  = blockIdx.y >> 4;
    const int h  = blockIdx.y & 15;
    const int tid = threadIdx.x;
    const float* vb = V + ((size_t)(n * Ll + l0)) * Ee + h * Dd;
    for (int idx = tid; idx < 64 * 16; idx += 256) {
        int r = idx >> 4, c4 = idx & 15;
        float4 v = *reinterpret_cast<const float4*>(vb + (size_t)r * Ee + c4 * 4);
        sm[r][c4 * 4 + 0] = v.x; sm[r][c4 * 4 + 1] = v.y;
        sm[r][c4 * 4 + 2] = v.z; sm[r][c4 * 4 + 3] = v.w;
    }
    __syncthreads();
    const int d = tid >> 2;
    const int lb = (tid & 3) * 16;
    __half* ob = g_vt + (((size_t)(n * Hh + h) * Dd + d)) * Ll + l0 + lb;
    uint32_t pk[8];
    #pragma unroll
    for (int i = 0; i < 8; i++)
        pk[i] = h2u(__floats2half2_rn(sm[lb + 2 * i][d], sm[lb + 2 * i + 1][d]));
    *reinterpret_cast<uint4*>(ob)     = make_uint4(pk[0], pk[1], pk[2], pk[3]);
    *reinterpret_cast<uint4*>(ob + 8) = make_uint4(pk[4], pk[5], pk[6], pk[7]);
}

// ===========================================================================
// Prepass 3: mask -> bitmask, 8 words per warp
// ===========================================================================
__global__ __launch_bounds__(256) void mask_pack(const int* __restrict__ M) {
    const size_t nwords = (size_t)Nn * Ll * (Ll / 32);
    size_t wbase = (((size_t)blockIdx.x * 256 + threadIdx.x) >> 5) * 8;
    int lane = threadIdx.x & 31;
    if (wbase >= nwords) return;
    int v[8];
    #pragma unroll
    for (int j = 0; j < 8; j++) v[j] = M[(wbase + j) * 32 + lane];
    uint32_t b[8];
    #pragma unroll
    for (int j = 0; j < 8; j++) b[j] = __ballot_sync(0xffffffffu, v[j] != 0);
    if (lane == 0) {
        *reinterpret_cast<uint4*>(&g_mask_bits[wbase])     = make_uint4(b[0], b[1], b[2], b[3]);
        *reinterpret_cast<uint4*>(&g_mask_bits[wbase + 4]) = make_uint4(b[4], b[5], b[6], b[7]);
    }
}

// ===========================================================================
// Flash attention, fused per-n16-subtile pipeline (QK_j -> exp_j -> PV_j).
// The PV k-slice IS the QK n-subtile, so fusion is exact. Live S regs drop
// 32 -> 8, Ap 16 -> 4 => 3 CTAs/SM via __launch_bounds__(256, 3).
// Grid (L/128, N*H) = (16, 32), 256 threads = 8 warps (16 q-rows each).
// ===========================================================================
#define SMQ_OFF 0
#define SMK_OFF (128 * SQH * 2)              // 18432
#define VOFF    (64 * SQH * 2)               // 9216 (V within stage)
#define STAGE   (2 * 64 * SQH * 2)           // K 64 + V 64 rows = 18432
#define SM_ATT_TOTAL (SMK_OFF + 2 * STAGE)   // 55296 B

__global__ __launch_bounds__(256, 3) void attn_hmma(
    const int* __restrict__ dummy)
{
    extern __shared__ __align__(16) char smem[];
    const uint32_t sb = smem_u32(smem);
    const int tid = threadIdx.x;
    const int lane = tid & 31;
    const int wid = tid >> 5;
    const int gid = lane >> 2, tig = lane & 3;
    const int n = blockIdx.y >> 4;
    const int h = blockIdx.y & 15;
    const int q0 = blockIdx.x * 128;
    const int m0w = wid * 16;

    // ---- preload Q (128 rows) + tile 0 (K/V) via cp.async ----
    {
        const __half* qb = g_qh + ((size_t)(n * Ll + q0)) * Ee + h * Dd;
        #pragma unroll
        for (int i = 0; i < 4; i++) {
            int idx = tid + i * 256;
            int r = idx >> 3, c = idx & 7;
            CPA16(sb + SMQ_OFF + r * 144 + c * 16, qb + (size_t)r * Ee + c * 8);
        }
        const __half* kb = g_kh + ((size_t)(n * Ll)) * Ee + h * Dd;
        const __half* vb = g_vt + ((size_t)(n * Hh + h) * Dd) * Ll;
        #pragma unroll
        for (int i = 0; i < 2; i++) {
            int idx = tid + i * 256;
            int r = idx >> 3, c = idx & 7;
            CPA16(sb + SMK_OFF + r * 144 + c * 16, kb + (size_t)r * Ee + c * 8);
            CPA16(sb + SMK_OFF + VOFF + r * 144 + c * 16, vb + (size_t)r * Ll + c * 8);
        }
        CPA_COMMIT();
    }

    float O[8][4];
    #pragma unroll
    for (int t = 0; t < 8; t++)
        #pragma unroll
        for (int j = 0; j < 4; j++) O[t][j] = 0.0f;
    float lsum0 = 0.0f, lsum1 = 0.0f;
    uint32_t qf[4][4];                       // Q fragments, loaded once

    const uint32_t aQrow = sb + SMQ_OFF + (m0w + (lane & 15)) * 144 + ((lane >> 4) << 4);
    const uint32_t bRowSel = (((lane >> 4) & 1) << 3) + (lane & 7);
    const uint32_t bKhi    = ((lane >> 3) & 1) << 4;
    const int sh = 2 * tig;

    const uint32_t* mb0 = g_mask_bits + ((size_t)(n * Ll + q0 + m0w + gid)) * (Ll / 32);
    const uint32_t* mb1 = mb0 + (size_t)8 * (Ll / 32);

    for (int kt = 0; kt < NT; kt++) {
        if (kt + 1 < NT) {
            const __half* kb = g_kh + ((size_t)(n * Ll + (kt + 1) * 64)) * Ee + h * Dd;
            const __half* vb = g_vt + ((size_t)(n * Hh + h) * Dd) * Ll + (kt + 1) * 64;
            uint32_t st = sb + SMK_OFF + ((kt + 1) & 1) * STAGE;
            #pragma unroll
            for (int i = 0; i < 2; i++) {
                int idx = tid + i * 256;
                int r = idx >> 3, c = idx & 7;
                CPA16(st + r * 144 + c * 16, kb + (size_t)r * Ee + c * 8);
                CPA16(st + VOFF + r * 144 + c * 16, vb + (size_t)r * Ll + c * 8);
            }
        }
        CPA_COMMIT();
        CPA_WAIT1();
        __syncthreads();

        if (kt == 0) {   // Q now resident: hoist fragments into registers
            #pragma unroll
            for (int kc = 0; kc < 4; kc++)
                ldmx4(qf[kc][0], qf[kc][1], qf[kc][2], qf[kc][3], aQrow + kc * 32);
        }

        const uint32_t kbase = sb + SMK_OFF + (kt & 1) * STAGE;
        const uint32_t vbase = kbase + VOFF;

        uint32_t w0a = mb0[kt * 2] >> sh, w0b = mb0[kt * 2 + 1] >> sh;
        uint32_t w1a = mb1[kt * 2] >> sh, w1b = mb1[kt * 2 + 1] >> sh;

        // ---- fused per-n16-subtile: QK_j -> mask+exp_j -> PV_j ----
        #pragma unroll
        for (int j = 0; j < 4; j++) {
            // S subtile j (keys 16j..16j+15): 2 n8 frags
            float s0[4] = {0.f, 0.f, 0.f, 0.f};
            float s1[4] = {0.f, 0.f, 0.f, 0.f};
            #pragma unroll
            for (int kc = 0; kc < 4; kc++) {
                uint32_t b0, b1, b2, b3;
                ldmx4(b0, b1, b2, b3,
                      kbase + (j * 16 + bRowSel) * 144 + kc * 32 + bKhi);
                mma16816(s0, qf[kc][0], qf[kc][1], qf[kc][2], qf[kc][3], b0, b1);
                mma16816(s1, qf[kc][0], qf[kc][1], qf[kc][2], qf[kc][3], b2, b3);
            }

            // mask + exp2 (packed fp16x2)
            uint32_t ba0 = (((2 * j < 4) ? w0a : w0b) >> ((2 * j & 3) * 8)) & 3u;
            uint32_t bb0 = (((2 * j < 4) ? w1a : w1b) >> ((2 * j & 3) * 8)) & 3u;
            uint32_t ba1 = ((((2 * j + 1) < 4) ? w0a : w0b) >> (((2 * j + 1) & 3) * 8)) & 3u;
            uint32_t bb1 = ((((2 * j + 1) < 4) ? w1a : w1b) >> (((2 * j + 1) & 3) * 8)) & 3u;
            uint32_t m00 = ((ba0 & 1u) ? 0x0000FFFFu : 0u) | ((ba0 & 2u) ? 0xFFFF0000u : 0u);
            uint32_t m10 = ((bb0 & 1u) ? 0x0000FFFFu : 0u) | ((bb0 & 2u) ? 0xFFFF0000u : 0u);
            uint32_t m01 = ((ba1 & 1u) ? 0x0000FFFFu : 0u) | ((ba1 & 2u) ? 0xFFFF0000u : 0u);
            uint32_t m11 = ((bb1 & 1u) ? 0x0000FFFFu : 0u) | ((bb1 & 2u) ? 0xFFFF0000u : 0u);
            // a0 = (row gid, k lo), a1 = (row gid+8, k lo), a2/a3 = k hi
            uint32_t a0 = ex2_h2(cvt_h2(s0[0], s0[1])) & m00;
            uint32_t a1 = ex2_h2(cvt_h2(s0[2], s0[3])) & m10;
            uint32_t a2 = ex2_h2(cvt_h2(s1[0], s1[1])) & m01;
            uint32_t a3 = ex2_h2(cvt_h2(s1[2], s1[3])) & m11;

            // row-sum contribution (fma pipe) + fp32 accumulate
            {
                uint32_t t0 = hadd2u(a0, a2);
                uint32_t t1 = hadd2u(a1, a3);
                float2 f0 = __half22float2(*reinterpret_cast<__half2*>(&t0));
                float2 f1 = __half22float2(*reinterpret_cast<__half2*>(&t1));
                lsum0 += f0.x + f0.y;
                lsum1 += f1.x + f1.y;
            }

            // PV: O += P_j (keys 16j..16j+15) x V rows 16j..16j+15
            #pragma unroll
            for (int jj = 0; jj < 4; jj++) {
                uint32_t v0, v1, v2, v3;
                ldmx4(v0, v1, v2, v3,
                      vbase + (jj * 16 + bRowSel) * 144 + j * 32 + bKhi);
                mma16816(O[2 * jj],     a0, a1, a2, a3, v0, v1);
                mma16816(O[2 * jj + 1], a0, a1, a2, a3, v2, v3);
            }
        }
        __syncthreads();
    }

    // ---- reduce row sums over the 4 tig lanes, normalize, store fp16 ----
    lsum0 += __shfl_xor_sync(0xffffffffu, lsum0, 1);
    lsum0 += __shfl_xor_sync(0xffffffffu, lsum0, 2);
    lsum1 += __shfl_xor_sync(0xffffffffu, lsum1, 1);
    lsum1 += __shfl_xor_sync(0xffffffffu, lsum1, 2);
    float inv0 = 1.0f / lsum0, inv1 = 1.0f / lsum1;

    __half* ob0 = g_attn_half + ((size_t)(n * Ll + q0 + m0w + gid)) * Ee + h * Dd;
    __half* ob1 = ob0 + (size_t)8 * Ee;
    #pragma unroll
    for (int t = 0; t < 8; t++) {
        *reinterpret_cast<uint32_t*>(ob0 + t * 8 + 2 * tig) =
            h2u(__floats2half2_rn(O[t][0] * inv0, O[t][1] * inv0));
        *reinterpret_cast<uint32_t*>(ob1 + t * 8 + 2 * tig) =
            h2u(__floats2half2_rn(O[t][2] * inv1, O[t][3] * inv1));
    }
}

// ===========================================================================
// Projection: out = X W^T + b. fp16 mma, CTA 128x128, warp tile m32 x n64.
// ===========================================================================
#define PJ_STAGE (2 * 128 * SQH * 2)
#define PJ_TOTAL (2 * PJ_STAGE)

__global__ __launch_bounds__(256) void proj_hmma(
    const float* __restrict__ bias, float* __restrict__ out)
{
    extern __shared__ __align__(16) char smem[];
    const uint32_t sb = smem_u32(smem);
    const int tid = threadIdx.x;
    const int lane = tid & 31;
    const int wid = tid >> 5;
    const int gid = lane >> 2, tig = lane & 3;
    const int n0 = blockIdx.x * 128;
    const int m0 = blockIdx.y * 128;
    const int mw = wid & 3, nw = wid >> 2;
    const int m0w = mw * 32;
    const int n0w = nw * 64;

    const uint32_t bRowSel = (((lane >> 4) & 1) << 3) + (lane & 7);
    const uint32_t bKhi    = ((lane >> 3) & 1) << 4;

    auto issue = [&](int kc) {
        const __half* xb = g_attn_half + (size_t)m0 * Ee + kc * 64;
        const __half* wb = g_wh + (size_t)n0 * Ee + kc * 64;
        uint32_t st = sb + (kc & 1) * PJ_STAGE;
        #pragma unroll
        for (int i = 0; i < 4; i++) {
            int idx = tid + i * 256;
            int r = idx >> 3, c = idx & 7;
            CPA16(st + r * 144 + c * 16, xb + (size_t)r * Ee + c * 8);
            CPA16(st + 128 * SQH * 2 + r * 144 + c * 16, wb + (size_t)r * Ee + c * 8);
        }
    };

    float C[2][8][4];   // [m-half][n8-tile][frag]
    #pragma unroll
    for (int hh = 0; hh < 2; hh++)
        #pragma unroll
        for (int t = 0; t < 8; t++)
            #pragma unroll
            for (int j = 0; j < 4; j++) C[hh][t][j] = 0.0f;

    issue(0);
    CPA_COMMIT();

    for (int kc = 0; kc < Ee / 64; kc++) {
        if (kc + 1 < Ee / 64) issue(kc + 1);
        CPA_COMMIT();
        CPA_WAIT1();
        __syncthreads();

        const uint32_t xbase = sb + (kc & 1) * PJ_STAGE;
        const uint32_t wbase = xbase + 128 * SQH * 2;

        #pragma unroll
        for (int k4 = 0; k4 < 4; k4++) {
            uint32_t a[2][4];
            #pragma unroll
            for (int hh = 0; hh < 2; hh++)
                ldmx4(a[hh][0], a[hh][1], a[hh][2], a[hh][3],
                      xbase + (m0w + hh * 16 + (lane & 15)) * 144 +
                      ((lane >> 4) << 4) + k4 * 32);
            #pragma unroll
            for (int j = 0; j < 4; j++) {
                uint32_t b0, b1, b2, b3;
                ldmx4(b0, b1, b2, b3,
                      wbase + (n0w + j * 16 + bRowSel) * 144 + k4 * 32 + bKhi);
                #pragma unroll
                for (int hh = 0; hh < 2; hh++) {
                    mma16816(C[hh][2 * j],     a[hh][0], a[hh][1], a[hh][2], a[hh][3], b0, b1);
                    mma16816(C[hh][2 * j + 1], a[hh][0], a[hh][1], a[hh][2], a[hh][3], b2, b3);
                }
            }
        }
        __syncthreads();
    }

    #pragma unroll
    for (int hh = 0; hh < 2; hh++) {
        float* ob0 = out + (size_t)(m0 + m0w + hh * 16 + gid) * Ee + n0 + n0w;
        float* ob1 = ob0 + (size_t)8 * Ee;
        #pragma unroll
        for (int t = 0; t < 8; t++) {
            float2 bv = *reinterpret_cast<const float2*>(bias + n0 + n0w + t * 8 + 2 * tig);
            *reinterpret_cast<float2*>(ob0 + t * 8 + 2 * tig) =
                make_float2(C[hh][t][0] + bv.x, C[hh][t][1] + bv.y);
            *reinterpret_cast<float2*>(ob1 + t * 8 + 2 * tig) =
                make_float2(C[hh][t][2] + bv.x, C[hh][t][3] + bv.y);
        }
    }
}

// ===========================================================================
extern "C" void kernel_launch(void* const* d_in, const int* in_sizes, int n_in,
                              void* d_out, int out_size)
{
    const float* Q = (const float*)d_in[0];
    const float* K = (const float*)d_in[1];
    const float* V = (const float*)d_in[2];
    const int*   M = (const int*)d_in[3];
    const float* W = (const float*)d_in[4];
    const float* b = (const float*)d_in[5];
    float* out = (float*)d_out;

    conv_qkw<<<2048, 256>>>(Q, K, W);
    {
        dim3 g(Ll / 64, Nn * Hh);
        v_transpose<<<g, 256>>>(V);
    }
    {
        size_t nwords = (size_t)Nn * Ll * (Ll / 32);
        size_t nwarps = (nwords + 7) / 8;
        mask_pack<<<(int)((nwarps + 7) / 8), 256>>>(M);
    }

    cudaFuncSetAttribute(attn_hmma,
                         cudaFuncAttributeMaxDynamicSharedMemorySize, SM_ATT_TOTAL);
    {
        dim3 g(Ll / 128, Nn * Hh);
        attn_hmma<<<g, 256, SM_ATT_TOTAL>>>(M);
    }

    cudaFuncSetAttribute(proj_hmma,
                         cudaFuncAttributeMaxDynamicSharedMemorySize, PJ_TOTAL);
    {
        dim3 g(Ee / 128, (Nn * Ll) / 128);
        proj_hmma<<<g, 256, PJ_TOTAL>>>(b, out);
    }
}

// round 9
// speedup vs baseline: 8.4252x; 1.0338x over previous
#include <cuda_runtime.h>
#include <cuda_fp16.h>
#include <cstdint>

// Problem constants
#define Nn 2
#define Ll 2048
#define Ee 1024
#define Hh 16
#define Dd 64
#define NT (Ll / 64)      // 32 key tiles
#define SQH 72            // smem row stride in halves (144 B)

// Static device scratch (allocation-free per harness rules)
__device__ __align__(16) __half   g_qh[(size_t)Nn * Ll * Ee];        // Q * log2e/32
__device__ __align__(16) __half   g_kh[(size_t)Nn * Ll * Ee];        // K fp16
__device__ __align__(16) __half   g_vt[(size_t)Nn * Hh * Dd * Ll];   // V fp16 transposed
__device__ __align__(16) __half   g_attn_half[(size_t)Nn * Ll * Ee]; // attention out fp16
__device__ __align__(16) __half   g_wh[(size_t)Ee * Ee];             // W fp16
__device__ __align__(16) uint32_t g_mask_bits[(size_t)Nn * Ll * (Ll / 32)];

// ---------------------------------------------------------------------------
// helpers
// ---------------------------------------------------------------------------
__device__ __forceinline__ uint32_t smem_u32(const void* p) {
    uint32_t a;
    asm("{ .reg .u64 t; cvta.to.shared.u64 t, %1; cvt.u32.u64 %0, t; }"
        : "=r"(a) : "l"(p));
    return a;
}

__device__ __forceinline__ void ldmx4(uint32_t& r0, uint32_t& r1,
                                      uint32_t& r2, uint32_t& r3, uint32_t addr) {
    asm volatile("ldmatrix.sync.aligned.m8n8.x4.shared.b16 {%0,%1,%2,%3}, [%4];"
                 : "=r"(r0), "=r"(r1), "=r"(r2), "=r"(r3) : "r"(addr));
}

// f32-accum variant (PV)
__device__ __forceinline__ void mma16816(float c[4], uint32_t a0, uint32_t a1,
                                         uint32_t a2, uint32_t a3,
                                         uint32_t b0, uint32_t b1) {
    asm volatile(
        "mma.sync.aligned.m16n8k16.row.col.f32.f16.f16.f32 "
        "{%0,%1,%2,%3},{%4,%5,%6,%7},{%8,%9},{%0,%1,%2,%3};"
        : "+f"(c[0]), "+f"(c[1]), "+f"(c[2]), "+f"(c[3])
        : "r"(a0), "r"(a1), "r"(a2), "r"(a3), "r"(b0), "r"(b1));
}

// f16-accum variant (QK): C/D = 2x f16x2 regs; c0 = row gid, c1 = row gid+8
__device__ __forceinline__ void mma16816h(uint32_t c[2], uint32_t a0, uint32_t a1,
                                          uint32_t a2, uint32_t a3,
                                          uint32_t b0, uint32_t b1) {
    asm volatile(
        "mma.sync.aligned.m16n8k16.row.col.f16.f16.f16.f16 "
        "{%0,%1},{%2,%3,%4,%5},{%6,%7},{%0,%1};"
        : "+r"(c[0]), "+r"(c[1])
        : "r"(a0), "r"(a1), "r"(a2), "r"(a3), "r"(b0), "r"(b1));
}

// 2^x on both halves
__device__ __forceinline__ uint32_t ex2_h2(uint32_t s) {
    uint32_t d;
    asm("ex2.approx.f16x2 %0, %1;" : "=r"(d) : "r"(s));
    return d;
}
// fp16x2 add (FMA-pipe)
__device__ __forceinline__ uint32_t hadd2u(uint32_t a, uint32_t b) {
    uint32_t d;
    asm("add.f16x2 %0, %1, %2;" : "=r"(d) : "r"(a), "r"(b));
    return d;
}

#define CPA16(dst, src) \
    asm volatile("cp.async.cg.shared.global [%0], [%1], 16;" :: "r"(dst), "l"(src))
#define CPA_COMMIT() asm volatile("cp.async.commit_group;" ::: "memory")
#define CPA_WAIT0()  asm volatile("cp.async.wait_group 0;" ::: "memory")

__device__ __forceinline__ uint32_t h2u(__half2 h) { return *reinterpret_cast<uint32_t*>(&h); }

// ===========================================================================
// Prepass 1: convert Q (scaled log2e/32), K, W to fp16
// ===========================================================================
#define EQ ((size_t)Nn * Ll * Ee)
#define EW ((size_t)Ee * Ee)
__global__ __launch_bounds__(256) void conv_qkw(
    const float* __restrict__ Q, const float* __restrict__ K,
    const float* __restrict__ W)
{
    const size_t q4 = EQ / 4, k4 = EQ / 4, w4 = EW / 4;
    const size_t tot = q4 + k4 + w4;
    const float QSC = 0.045084437f;   // log2(e)/32
    for (size_t i = (size_t)blockIdx.x * 256 + threadIdx.x; i < tot;
         i += (size_t)gridDim.x * 256) {
        const float* src; __half* dst; float sc; size_t j;
        if (i < q4)            { src = Q; dst = g_qh; sc = QSC; j = i; }
        else if (i < q4 + k4)  { src = K; dst = g_kh; sc = 1.0f; j = i - q4; }
        else                   { src = W; dst = g_wh; sc = 1.0f; j = i - q4 - k4; }
        float4 v = reinterpret_cast<const float4*>(src)[j];
        __half2 h0 = __floats2half2_rn(v.x * sc, v.y * sc);
        __half2 h1 = __floats2half2_rn(v.z * sc, v.w * sc);
        reinterpret_cast<uint2*>(dst)[j] = make_uint2(h2u(h0), h2u(h1));
    }
}

// ===========================================================================
// Prepass 2: V -> fp16 transposed g_vt[n][h][d][l]
// ===========================================================================
__global__ __launch_bounds__(256) void v_transpose(const float* __restrict__ V) {
    __shared__ float sm[64][65];
    const int l0 = blockIdx.x * 64;
    const int n  = blockIdx.y >> 4;
    const int h  = blockIdx.y & 15;
    const int tid = threadIdx.x;
    const float* vb = V + ((size_t)(n * Ll + l0)) * Ee + h * Dd;
    for (int idx = tid; idx < 64 * 16; idx += 256) {
        int r = idx >> 4, c4 = idx & 15;
        float4 v = *reinterpret_cast<const float4*>(vb + (size_t)r * Ee + c4 * 4);
        sm[r][c4 * 4 + 0] = v.x; sm[r][c4 * 4 + 1] = v.y;
        sm[r][c4 * 4 + 2] = v.z; sm[r][c4 * 4 + 3] = v.w;
    }
    __syncthreads();
    const int d = tid >> 2;
    const int lb = (tid & 3) * 16;
    __half* ob = g_vt + (((size_t)(n * Hh + h) * Dd + d)) * Ll + l0 + lb;
    uint32_t pk[8];
    #pragma unroll
    for (int i = 0; i < 8; i++)
        pk[i] = h2u(__floats2half2_rn(sm[lb + 2 * i][d], sm[lb + 2 * i + 1][d]));
    *reinterpret_cast<uint4*>(ob)     = make_uint4(pk[0], pk[1], pk[2], pk[3]);
    *reinterpret_cast<uint4*>(ob + 8) = make_uint4(pk[4], pk[5], pk[6], pk[7]);
}

// ===========================================================================
// Prepass 3: mask -> bitmask, 8 words per warp
// ===========================================================================
__global__ __launch_bounds__(256) void mask_pack(const int* __restrict__ M) {
    const size_t nwords = (size_t)Nn * Ll * (Ll / 32);
    size_t wbase = (((size_t)blockIdx.x * 256 + threadIdx.x) >> 5) * 8;
    int lane = threadIdx.x & 31;
    if (wbase >= nwords) return;
    int v[8];
    #pragma unroll
    for (int j = 0; j < 8; j++) v[j] = M[(wbase + j) * 32 + lane];
    uint32_t b[8];
    #pragma unroll
    for (int j = 0; j < 8; j++) b[j] = __ballot_sync(0xffffffffu, v[j] != 0);
    if (lane == 0) {
        *reinterpret_cast<uint4*>(&g_mask_bits[wbase])     = make_uint4(b[0], b[1], b[2], b[3]);
        *reinterpret_cast<uint4*>(&g_mask_bits[wbase + 4]) = make_uint4(b[4], b[5], b[6], b[7]);
    }
}

// ===========================================================================
// Flash attention. QK in fp16-accum mma (S emerges packed fp16x2 -> ex2
// directly, no cvt; 2x tensor rate for QK). PV in fp32-accum. Fused
// per-n16-subtile pipeline; one __syncthreads per tile.
// Grid (L/128, N*H) = (16, 32), 256 threads = 8 warps (16 q-rows each).
// ===========================================================================
#define SMQ_OFF 0
#define SMK_OFF (128 * SQH * 2)              // 18432
#define VOFF    (64 * SQH * 2)               // 9216 (V within stage)
#define STAGE   (2 * 64 * SQH * 2)           // K 64 + V 64 rows = 18432
#define SM_ATT_TOTAL (SMK_OFF + 2 * STAGE)   // 55296 B

__global__ __launch_bounds__(256, 3) void attn_hmma(
    const int* __restrict__ dummy)
{
    extern __shared__ __align__(16) char smem[];
    const uint32_t sb = smem_u32(smem);
    const int tid = threadIdx.x;
    const int lane = tid & 31;
    const int wid = tid >> 5;
    const int gid = lane >> 2, tig = lane & 3;
    const int n = blockIdx.y >> 4;
    const int h = blockIdx.y & 15;
    const int q0 = blockIdx.x * 128;
    const int m0w = wid * 16;

    // ---- preload Q (128 rows) + tile 0 (K/V) via cp.async ----
    {
        const __half* qb = g_qh + ((size_t)(n * Ll + q0)) * Ee + h * Dd;
        #pragma unroll
        for (int i = 0; i < 4; i++) {
            int idx = tid + i * 256;
            int r = idx >> 3, c = idx & 7;
            CPA16(sb + SMQ_OFF + r * 144 + c * 16, qb + (size_t)r * Ee + c * 8);
        }
        const __half* kb = g_kh + ((size_t)(n * Ll)) * Ee + h * Dd;
        const __half* vb = g_vt + ((size_t)(n * Hh + h) * Dd) * Ll;
        #pragma unroll
        for (int i = 0; i < 2; i++) {
            int idx = tid + i * 256;
            int r = idx >> 3, c = idx & 7;
            CPA16(sb + SMK_OFF + r * 144 + c * 16, kb + (size_t)r * Ee + c * 8);
            CPA16(sb + SMK_OFF + VOFF + r * 144 + c * 16, vb + (size_t)r * Ll + c * 8);
        }
        CPA_COMMIT();
    }

    float O[8][4];
    #pragma unroll
    for (int t = 0; t < 8; t++)
        #pragma unroll
        for (int j = 0; j < 4; j++) O[t][j] = 0.0f;
    float lsum0 = 0.0f, lsum1 = 0.0f;
    uint32_t qf[4][4];                       // Q fragments, loaded once

    const uint32_t aQrow = sb + SMQ_OFF + (m0w + (lane & 15)) * 144 + ((lane >> 4) << 4);
    const uint32_t bRowSel = (((lane >> 4) & 1) << 3) + (lane & 7);
    const uint32_t bKhi    = ((lane >> 3) & 1) << 4;
    const int sh = 2 * tig;

    const uint32_t* mb0 = g_mask_bits + ((size_t)(n * Ll + q0 + m0w + gid)) * (Ll / 32);
    const uint32_t* mb1 = mb0 + (size_t)8 * (Ll / 32);

    for (int kt = 0; kt < NT; kt++) {
        // tile kt data arrived; barrier also proves everyone finished reading
        // the stage that prefetch(kt+1) will overwrite.
        CPA_WAIT0();
        __syncthreads();

        if (kt == 0) {   // Q resident: hoist fragments into registers
            #pragma unroll
            for (int kc = 0; kc < 4; kc++)
                ldmx4(qf[kc][0], qf[kc][1], qf[kc][2], qf[kc][3], aQrow + kc * 32);
        }

        // prefetch next tile into the other stage (overlaps compute below)
        if (kt + 1 < NT) {
            const __half* kb = g_kh + ((size_t)(n * Ll + (kt + 1) * 64)) * Ee + h * Dd;
            const __half* vb = g_vt + ((size_t)(n * Hh + h) * Dd) * Ll + (kt + 1) * 64;
            uint32_t st = sb + SMK_OFF + ((kt + 1) & 1) * STAGE;
            #pragma unroll
            for (int i = 0; i < 2; i++) {
                int idx = tid + i * 256;
                int r = idx >> 3, c = idx & 7;
                CPA16(st + r * 144 + c * 16, kb + (size_t)r * Ee + c * 8);
                CPA16(st + VOFF + r * 144 + c * 16, vb + (size_t)r * Ll + c * 8);
            }
            CPA_COMMIT();
        }

        const uint32_t kbase = sb + SMK_OFF + (kt & 1) * STAGE;
        const uint32_t vbase = kbase + VOFF;

        uint32_t w0a = mb0[kt * 2] >> sh, w0b = mb0[kt * 2 + 1] >> sh;
        uint32_t w1a = mb1[kt * 2] >> sh, w1b = mb1[kt * 2 + 1] >> sh;

        // ---- fused per-n16-subtile: QK_j (f16 accum) -> mask+exp_j -> PV_j ----
        #pragma unroll
        for (int j = 0; j < 4; j++) {
            // S subtile j (keys 16j..16j+15), fp16 accumulators
            uint32_t s0[2] = {0u, 0u};   // n8#0: [row gid | row gid+8] pairs
            uint32_t s1[2] = {0u, 0u};   // n8#1
            #pragma unroll
            for (int kc = 0; kc < 4; kc++) {
                uint32_t b0, b1, b2, b3;
                ldmx4(b0, b1, b2, b3,
                      kbase + (j * 16 + bRowSel) * 144 + kc * 32 + bKhi);
                mma16816h(s0, qf[kc][0], qf[kc][1], qf[kc][2], qf[kc][3], b0, b1);
                mma16816h(s1, qf[kc][0], qf[kc][1], qf[kc][2], qf[kc][3], b2, b3);
            }

            // mask half-words (t = 2j for n8#0, t = 2j+1 for n8#1)
            uint32_t ba0 = (((2 * j < 4) ? w0a : w0b) >> ((2 * j & 3) * 8)) & 3u;
            uint32_t bb0 = (((2 * j < 4) ? w1a : w1b) >> ((2 * j & 3) * 8)) & 3u;
            uint32_t ba1 = ((((2 * j + 1) < 4) ? w0a : w0b) >> (((2 * j + 1) & 3) * 8)) & 3u;
            uint32_t bb1 = ((((2 * j + 1) < 4) ? w1a : w1b) >> (((2 * j + 1) & 3) * 8)) & 3u;
            uint32_t m00 = ((ba0 & 1u) ? 0x0000FFFFu : 0u) | ((ba0 & 2u) ? 0xFFFF0000u : 0u);
            uint32_t m10 = ((bb0 & 1u) ? 0x0000FFFFu : 0u) | ((bb0 & 2u) ? 0xFFFF0000u : 0u);
            uint32_t m01 = ((ba1 & 1u) ? 0x0000FFFFu : 0u) | ((ba1 & 2u) ? 0xFFFF0000u : 0u);
            uint32_t m11 = ((bb1 & 1u) ? 0x0000FFFFu : 0u) | ((bb1 & 2u) ? 0xFFFF0000u : 0u);

            // P = exp2(S) directly on packed mma output (no cvt!)
            uint32_t a0 = ex2_h2(s0[0]) & m00;   // row gid,   k lo pair
            uint32_t a1 = ex2_h2(s0[1]) & m10;   // row gid+8, k lo pair
            uint32_t a2 = ex2_h2(s1[0]) & m01;   // row gid,   k hi pair
            uint32_t a3 = ex2_h2(s1[1]) & m11;   // row gid+8, k hi pair

            // row-sum contribution (fma pipe) + fp32 accumulate
            {
                uint32_t t0 = hadd2u(a0, a2);
                uint32_t t1 = hadd2u(a1, a3);
                float2 f0 = __half22float2(*reinterpret_cast<__half2*>(&t0));
                float2 f1 = __half22float2(*reinterpret_cast<__half2*>(&t1));
                lsum0 += f0.x + f0.y;
                lsum1 += f1.x + f1.y;
            }

            // PV: O += P_j x V rows 16j..16j+15 (f32 accum)
            #pragma unroll
            for (int jj = 0; jj < 4; jj++) {
                uint32_t v0, v1, v2, v3;
                ldmx4(v0, v1, v2, v3,
                      vbase + (jj * 16 + bRowSel) * 144 + j * 32 + bKhi);
                mma16816(O[2 * jj],     a0, a1, a2, a3, v0, v1);
                mma16816(O[2 * jj + 1], a0, a1, a2, a3, v2, v3);
            }
        }
    }

    // ---- reduce row sums over the 4 tig lanes, normalize, store fp16 ----
    lsum0 += __shfl_xor_sync(0xffffffffu, lsum0, 1);
    lsum0 += __shfl_xor_sync(0xffffffffu, lsum0, 2);
    lsum1 += __shfl_xor_sync(0xffffffffu, lsum1, 1);
    lsum1 += __shfl_xor_sync(0xffffffffu, lsum1, 2);
    float inv0 = 1.0f / lsum0, inv1 = 1.0f / lsum1;

    __half* ob0 = g_attn_half + ((size_t)(n * Ll + q0 + m0w + gid)) * Ee + h * Dd;
    __half* ob1 = ob0 + (size_t)8 * Ee;
    #pragma unroll
    for (int t = 0; t < 8; t++) {
        *reinterpret_cast<uint32_t*>(ob0 + t * 8 + 2 * tig) =
            h2u(__floats2half2_rn(O[t][0] * inv0, O[t][1] * inv0));
        *reinterpret_cast<uint32_t*>(ob1 + t * 8 + 2 * tig) =
            h2u(__floats2half2_rn(O[t][2] * inv1, O[t][3] * inv1));
    }
}

// ===========================================================================
// Projection: out = X W^T + b. fp16 mma (f32 accum), CTA 128x128,
// warp tile m32 x n64.
// ===========================================================================
#define PJ_STAGE (2 * 128 * SQH * 2)
#define PJ_TOTAL (2 * PJ_STAGE)

__global__ __launch_bounds__(256) void proj_hmma(
    const float* __restrict__ bias, float* __restrict__ out)
{
    extern __shared__ __align__(16) char smem[];
    const uint32_t sb = smem_u32(smem);
    const int tid = threadIdx.x;
    const int lane = tid & 31;
    const int wid = tid >> 5;
    const int gid = lane >> 2, tig = lane & 3;
    const int n0 = blockIdx.x * 128;
    const int m0 = blockIdx.y * 128;
    const int mw = wid & 3, nw = wid >> 2;
    const int m0w = mw * 32;
    const int n0w = nw * 64;

    const uint32_t bRowSel = (((lane >> 4) & 1) << 3) + (lane & 7);
    const uint32_t bKhi    = ((lane >> 3) & 1) << 4;

    auto issue = [&](int kc) {
        const __half* xb = g_attn_half + (size_t)m0 * Ee + kc * 64;
        const __half* wb = g_wh + (size_t)n0 * Ee + kc * 64;
        uint32_t st = sb + (kc & 1) * PJ_STAGE;
        #pragma unroll
        for (int i = 0; i < 4; i++) {
            int idx = tid + i * 256;
            int r = idx >> 3, c = idx & 7;
            CPA16(st + r * 144 + c * 16, xb + (size_t)r * Ee + c * 8);
            CPA16(st + 128 * SQH * 2 + r * 144 + c * 16, wb + (size_t)r * Ee + c * 8);
        }
        CPA_COMMIT();
    };

    float C[2][8][4];   // [m-half][n8-tile][frag]
    #pragma unroll
    for (int hh = 0; hh < 2; hh++)
        #pragma unroll
        for (int t = 0; t < 8; t++)
            #pragma unroll
            for (int j = 0; j < 4; j++) C[hh][t][j] = 0.0f;

    issue(0);

    for (int kc = 0; kc < Ee / 64; kc++) {
        CPA_WAIT0();
        __syncthreads();
        if (kc + 1 < Ee / 64) issue(kc + 1);

        const uint32_t xbase = sb + (kc & 1) * PJ_STAGE;
        const uint32_t wbase = xbase + 128 * SQH * 2;

        #pragma unroll
        for (int k4 = 0; k4 < 4; k4++) {
            uint32_t a[2][4];
            #pragma unroll
            for (int hh = 0; hh < 2; hh++)
                ldmx4(a[hh][0], a[hh][1], a[hh][2], a[hh][3],
                      xbase + (m0w + hh * 16 + (lane & 15)) * 144 +
                      ((lane >> 4) << 4) + k4 * 32);
            #pragma unroll
            for (int j = 0; j < 4; j++) {
                uint32_t b0, b1, b2, b3;
                ldmx4(b0, b1, b2, b3,
                      wbase + (n0w + j * 16 + bRowSel) * 144 + k4 * 32 + bKhi);
                #pragma unroll
                for (int hh = 0; hh < 2; hh++) {
                    mma16816(C[hh][2 * j],     a[hh][0], a[hh][1], a[hh][2], a[hh][3], b0, b1);
                    mma16816(C[hh][2 * j + 1], a[hh][0], a[hh][1], a[hh][2], a[hh][3], b2, b3);
                }
            }
        }
    }

    #pragma unroll
    for (int hh = 0; hh < 2; hh++) {
        float* ob0 = out + (size_t)(m0 + m0w + hh * 16 + gid) * Ee + n0 + n0w;
        float* ob1 = ob0 + (size_t)8 * Ee;
        #pragma unroll
        for (int t = 0; t < 8; t++) {
            float2 bv = *reinterpret_cast<const float2*>(bias + n0 + n0w + t * 8 + 2 * tig);
            *reinterpret_cast<float2*>(ob0 + t * 8 + 2 * tig) =
                make_float2(C[hh][t][0] + bv.x, C[hh][t][1] + bv.y);
            *reinterpret_cast<float2*>(ob1 + t * 8 + 2 * tig) =
                make_float2(C[hh][t][2] + bv.x, C[hh][t][3] + bv.y);
        }
    }
}

// ===========================================================================
extern "C" void kernel_launch(void* const* d_in, const int* in_sizes, int n_in,
                              void* d_out, int out_size)
{
    const float* Q = (const float*)d_in[0];
    const float* K = (const float*)d_in[1];
    const float* V = (const float*)d_in[2];
    const int*   M = (const int*)d_in[3];
    const float* W = (const float*)d_in[4];
    const float* b = (const float*)d_in[5];
    float* out = (float*)d_out;

    conv_qkw<<<2048, 256>>>(Q, K, W);
    {
        dim3 g(Ll / 64, Nn * Hh);
        v_transpose<<<g, 256>>>(V);
    }
    {
        size_t nwords = (size_t)Nn * Ll * (Ll / 32);
        size_t nwarps = (nwords + 7) / 8;
        mask_pack<<<(int)((nwarps + 7) / 8), 256>>>(M);
    }

    cudaFuncSetAttribute(attn_hmma,
                         cudaFuncAttributeMaxDynamicSharedMemorySize, SM_ATT_TOTAL);
    {
        dim3 g(Ll / 128, Nn * Hh);
        attn_hmma<<<g, 256, SM_ATT_TOTAL>>>(M);
    }

    cudaFuncSetAttribute(proj_hmma,
                         cudaFuncAttributeMaxDynamicSharedMemorySize, PJ_TOTAL);
    {
        dim3 g(Ee / 128, (Nn * Ll) / 128);
        proj_hmma<<<g, 256, PJ_TOTAL>>>(b, out);
    }
}